// round 1
// baseline (speedup 1.0000x reference)
#include <cuda_runtime.h>
#include <math.h>

#define KNB 32
#define NMX 8
#define RCUT 5.0f

// ---- per-launch precomputed effective weights (written by prep kernel) ----
__device__ float  g_wse[80];     // struct weights / scale
__device__ float  g_wme[251];    // mag weights / scale
__device__ float4 g_wdA[16];     // dmi weights (64)     = wm[16+83+p]/scale
__device__ float4 g_wdB[16];     // dmi-mix weights (64) = wm[16+163+p]/scale
__device__ float  g_espec[3];    // per-species: emb·(ws+wm) + atomic_energy_shift
__device__ float  g_c0;          // b_s + b_m - sum(shift * w/scale)

__device__ const int TUA[36] = {0,0,0,0,0,0,0,0, 1,1,1,1,1,1,1, 2,2,2,2,2,2,
                                3,3,3,3,3, 4,4,4,4, 5,5,5, 6,6, 7};
__device__ const int TUB[36] = {0,1,2,3,4,5,6,7, 1,2,3,4,5,6,7, 2,3,4,5,6,7,
                                3,4,5,6,7, 4,5,6,7, 5,6,7, 6,7, 7};

__global__ void prep_kernel(const float* __restrict__ ws, const float* __restrict__ sscale,
                            const float* __restrict__ sshift,
                            const float* __restrict__ wm, const float* __restrict__ mscale,
                            const float* __restrict__ mshift,
                            const float* __restrict__ emb, const float* __restrict__ aes,
                            const float* __restrict__ bs, const float* __restrict__ bm) {
    int t = threadIdx.x;
    if (t < 80)  g_wse[t] = ws[16 + t] / sscale[t];
    if (t < 251) g_wme[t] = wm[16 + t] / mscale[t];
    if (t < 64) {
        ((float*)g_wdA)[t] = wm[16 + 83 + t] / mscale[83 + t];
        ((float*)g_wdB)[t] = wm[16 + 163 + t] / mscale[163 + t];
    }
    if (t < 3) {
        float s = 0.0f;
        for (int k = 0; k < 16; k++) s += emb[t*16 + k] * (ws[k] + wm[k]);
        g_espec[t] = s + aes[t];
    }
    __syncthreads();
    if (t < 32) {
        float c = 0.0f;
        for (int d = t; d < 80;  d += 32) c -= sshift[d] * g_wse[d];
        for (int d = t; d < 251; d += 32) c -= mshift[d] * g_wme[d];
        #pragma unroll
        for (int o = 16; o > 0; o >>= 1) c += __shfl_xor_sync(0xffffffffu, c, o);
        if (t == 0) g_c0 = c + bs[0] + bm[0];
    }
}

// smem layout (floats): [0,684) coeff float4 area (9 pairs * 19 float4 rows)
//                       [684 + w*4384) per-warp partial stage (32 lanes * 137)
//                       [684 + 4*4384 + w*184) per-warp sums region:
//                           0..7 rad | 8..31 P | 32..79 Q6 | 80..103 M |
//                           104..111 namp | 112..135 W | 136..159 mQ | 160..183 cc
#define SM_COEFF 684
#define SM_PARTW 4384
#define SM_SUMW  184
#define SM_FLOATS (SM_COEFF + 4*SM_PARTW + 4*SM_SUMW)

__global__ __launch_bounds__(128, 3)
void magpot_kernel(const float* __restrict__ pos, const int* __restrict__ species,
                   const float* __restrict__ mag, const int* __restrict__ eidx,
                   const float* __restrict__ shifts, const float* __restrict__ rbc,
                   float* __restrict__ out, int N, int E) {
    extern __shared__ float smem[];
    float4* c4 = (float4*)smem;
    int tid = threadIdx.x, lane = tid & 31, warp = tid >> 5;

    // stage chebyshev->phi coefficients as float4, row stride 19 float4 per pair
    const float4* rbc4 = (const float4*)rbc;
    for (int t = tid; t < 9*16; t += blockDim.x) {
        int pr = t >> 4, q = t & 15;
        c4[pr*19 + q] = rbc4[pr*16 + q];
    }
    __syncthreads();

    int atom = blockIdx.x*4 + warp;
    if (atom >= N) return;

    float* sp = smem + SM_COEFF + warp*SM_PARTW;
    float* S  = smem + SM_COEFF + 4*SM_PARTW + warp*SM_SUMW;

    // ---------------- edge phase: lane = edge ----------------
    int e = atom*KNB + lane;
    int j = eidx[E + e];
    float pix = pos[atom*3+0], piy = pos[atom*3+1], piz = pos[atom*3+2];
    float rx = pos[j*3+0] - pix + shifts[e*3+0];
    float ry = pos[j*3+1] - piy + shifts[e*3+1];
    float rz = pos[j*3+2] - piz + shifts[e*3+2];
    float dist = sqrtf(rx*rx + ry*ry + rz*rz);

    float fc = (dist < RCUT) ? (0.5f*__cosf(3.14159265358979f*dist*(1.0f/RCUT)) + 0.5f) : 0.0f;
    float xr = dist*(1.0f/RCUT);
    float xc = 2.0f*xr*xr - 1.0f;
    float f[8];
    {
        float t0 = 1.0f, t1 = xc;
        f[0] = fc;
        f[1] = 0.5f*(t1 + 1.0f)*fc;
        #pragma unroll
        for (int n = 2; n < 8; n++) { float t2 = 2.0f*xc*t1 - t0; f[n] = 0.5f*(t2+1.0f)*fc; t0 = t1; t1 = t2; }
    }
    int spi = species[atom];
    int pair = spi*3 + species[j];
    float phi[8];
    #pragma unroll
    for (int n = 0; n < 8; n++) {
        float4 a = c4[pair*19 + n*2], b = c4[pair*19 + n*2 + 1];
        phi[n] = a.x*f[0] + a.y*f[1] + a.z*f[2] + a.w*f[3]
               + b.x*f[4] + b.y*f[5] + b.z*f[6] + b.w*f[7];
    }
    float invd = 1.0f / fmaxf(dist, 1e-8f);
    float hx = rx*invd, hy = ry*invd, hz = rz*invd;
    float mjx = mag[j*3+0], mjy = mag[j*3+1], mjz = mag[j*3+2];
    float uj = mjx*mjx + mjy*mjy + mjz*mjz;
    float mn = sqrtf(uj);
    float im = (mn > 1e-8f) ? (1.0f/mn) : 0.0f;
    float mdjx = mjx*im, mdjy = mjy*im, mdjz = mjz*im;
    const float THIRD = 1.0f/3.0f;
    float t60 = hx*hx - THIRD, t61 = hy*hy - THIRD, t62 = hz*hz - THIRD;
    float t63 = hx*hy, t64 = hx*hz, t65 = hy*hz;

    // stage 136 per-lane partials (stride 137 -> conflict-free)
    float* myp = sp + lane*137;
    #pragma unroll
    for (int n = 0; n < 8; n++) {
        float ph = phi[n];
        float pu = ph*uj;
        myp[n]          = ph;
        myp[8+n*3+0]    = ph*hx;  myp[8+n*3+1]   = ph*hy;  myp[8+n*3+2]   = ph*hz;
        myp[32+n*6+0]   = ph*t60; myp[32+n*6+1]  = ph*t61; myp[32+n*6+2]  = ph*t62;
        myp[32+n*6+3]   = ph*t63; myp[32+n*6+4]  = ph*t64; myp[32+n*6+5]  = ph*t65;
        myp[80+n*3+0]   = ph*mdjx; myp[80+n*3+1] = ph*mdjy; myp[80+n*3+2] = ph*mdjz;
        myp[104+n]      = pu;
        myp[112+n*3+0]  = pu*mdjx; myp[112+n*3+1] = pu*mdjy; myp[112+n*3+2] = pu*mdjz;
    }
    __syncwarp();

    // transpose-reduce: lane sums value columns
    for (int v = lane; v < 136; v += 32) {
        float s0 = 0.0f, s1 = 0.0f;
        #pragma unroll
        for (int l = 0; l < 16; l++) {
            s0 += sp[l*137 + v];
            s1 += sp[(l+16)*137 + v];
        }
        S[v] = s0 + s1;
    }
    __syncwarp();

    // ---------------- atom phase ----------------
    float mixv = mag[atom*3+0], miy = mag[atom*3+1], miz = mag[atom*3+2];
    float u = mixv*mixv + miy*miy + miz*miz;
    float mnorm = sqrtf(u);
    float imi = (mnorm > 1e-8f) ? (1.0f/mnorm) : 0.0f;
    float mdx = mixv*imi, mdy = miy*imi, mdz = miz*imi;

    // distributed: mQ[n][c] = (mdir . Q[n])_c ; cc[m][c] = (mdir x M[m])_c
    if (lane < 24) {
        int n = lane / 3, c = lane - n*3;
        float q0 = S[32 + n*6 + ((c==0) ? 0 : (c+2))];
        float q1 = S[32 + n*6 + ((c==1) ? 1 : (c+3))];
        float q2 = S[32 + n*6 + ((c==2) ? 2 : (c+4))];
        S[136 + lane] = q0*mdx + q1*mdy + q2*mdz;
        int c1 = (c+1) % 3, c2 = (c+2) % 3;
        float md1 = (c1==0) ? mdx : ((c1==1) ? mdy : mdz);
        float md2 = (c2==0) ? mdx : ((c2==1) ? mdy : mdz);
        S[160 + lane] = md1*S[80+n*3+c2] - md2*S[80+n*3+c1];
    }
    __syncwarp();

    float e_acc = (lane == 0) ? (g_c0 + g_espec[spi]) : 0.0f;

    // struct descriptors: radial(8) + PP triu(36) + QQ triu(36)
    for (int d = lane; d < 80; d += 32) {
        float val;
        if (d < 8) {
            val = S[d];
        } else if (d < 44) {
            int p = d - 8; int a = TUA[p], b = TUB[p];
            val = S[8+a*3]*S[8+b*3] + S[8+a*3+1]*S[8+b*3+1] + S[8+a*3+2]*S[8+b*3+2];
        } else {
            int p = d - 44; int a = TUA[p], b = TUB[p];
            const float* qa = S + 32 + a*6;
            const float* qb = S + 32 + b*6;
            val = qa[0]*qb[0] + qa[1]*qb[1] + qa[2]*qb[2]
                + 2.0f*(qa[3]*qb[3] + qa[4]*qb[4] + qa[5]*qb[5]);
        }
        e_acc += val * g_wse[d];
    }

    // mag descriptors (amp, iso, sia, sae, nbr_amp, nbr_ex; mixes folded into weights)
    for (int t = lane; t < 99; t += 32) {
        int flat = (t < 83) ? t : (t + 144);
        float val, wt;
        if (flat < 3) {
            val = (flat == 0) ? u : ((flat == 1) ? u*u : u*u*u);
            wt = g_wme[flat];
        } else if (flat < 11) {
            int n = flat - 3;
            val = mdx*S[80+n*3] + mdy*S[80+n*3+1] + mdz*S[80+n*3+2];
            wt = g_wme[flat] + u*g_wme[147+n];
        } else if (flat < 19) {
            int n = flat - 11;
            val = mdx*S[136+n*3] + mdy*S[136+n*3+1] + mdz*S[136+n*3+2];
            wt = g_wme[flat] + u*g_wme[155+n];
        } else if (flat < 83) {
            int p = flat - 19; int m = p >> 3, n2 = p & 7;
            val = S[136+m*3]*S[80+n2*3] + S[136+m*3+1]*S[80+n2*3+1] + S[136+m*3+2]*S[80+n2*3+2];
            wt = g_wme[flat];
        } else if (flat < 235) {
            int n = flat - 227;
            val = S[104+n];
            wt = g_wme[flat];
        } else {
            int n = flat - 235;
            val = mdx*S[112+n*3] + mdy*S[112+n*3+1] + mdz*S[112+n*3+2];
            wt = g_wme[flat] + u*g_wme[243+n];
        }
        e_acc += val * wt;
    }

    // ---------------- DMI via exclusive prefix scan over lanes ----------------
    float ccx[8], ccy[8], ccz[8];
    #pragma unroll
    for (int m = 0; m < 8; m++) {
        ccx[m] = S[160+m*3]; ccy[m] = S[160+m*3+1]; ccz[m] = S[160+m*3+2];
    }
    float pxs[8], pys[8], pzs[8];
    #pragma unroll
    for (int n = 0; n < 8; n++) {
        float vx = phi[n]*rx, vy = phi[n]*ry, vz = phi[n]*rz;
        float sx = vx, sy = vy, sz = vz;
        #pragma unroll
        for (int o = 1; o < 32; o <<= 1) {
            float ox = __shfl_up_sync(0xffffffffu, sx, o);
            float oy = __shfl_up_sync(0xffffffffu, sy, o);
            float oz = __shfl_up_sync(0xffffffffu, sz, o);
            if (lane >= o) { sx += ox; sy += oy; sz += oz; }
        }
        pxs[n] = sx - vx; pys[n] = sy - vy; pzs[n] = sz - vz;
    }
    #pragma unroll
    for (int n = 0; n < 8; n++) {
        float4 a0 = g_wdA[2*n], a1 = g_wdA[2*n+1];
        float4 b0 = g_wdB[2*n], b1 = g_wdB[2*n+1];
        float w[8];
        w[0] = a0.x + u*b0.x; w[1] = a0.y + u*b0.y; w[2] = a0.z + u*b0.z; w[3] = a0.w + u*b0.w;
        w[4] = a1.x + u*b1.x; w[5] = a1.y + u*b1.y; w[6] = a1.z + u*b1.z; w[7] = a1.w + u*b1.w;
        float tnx = 0.0f, tny = 0.0f, tnz = 0.0f;
        #pragma unroll
        for (int m = 0; m < 8; m++) {
            float s = phi[m]*w[m];
            tnx += s*ccx[m]; tny += s*ccy[m]; tnz += s*ccz[m];
        }
        float qx = ry*tnz - rz*tny;
        float qy = rz*tnx - rx*tnz;
        float qz = rx*tny - ry*tnx;
        e_acc += pxs[n]*qx + pys[n]*qy + pzs[n]*qz;
    }

    // final energy reduce
    #pragma unroll
    for (int o = 16; o > 0; o >>= 1) e_acc += __shfl_xor_sync(0xffffffffu, e_acc, o);
    if (lane == 0) out[atom] = e_acc;
}

extern "C" void kernel_launch(void* const* d_in, const int* in_sizes, int n_in,
                              void* d_out, int out_size) {
    const float* pos     = (const float*)d_in[0];
    const int*   species = (const int*)  d_in[1];
    const float* mag     = (const float*)d_in[2];
    const int*   eidx    = (const int*)  d_in[3];
    const float* shifts  = (const float*)d_in[4];
    const float* rbc     = (const float*)d_in[5];
    const float* emb     = (const float*)d_in[6];
    const float* sshift  = (const float*)d_in[7];
    const float* sscale  = (const float*)d_in[8];
    const float* mshift  = (const float*)d_in[9];
    const float* mscale  = (const float*)d_in[10];
    const float* aes     = (const float*)d_in[11];
    const float* ws      = (const float*)d_in[12];
    const float* bs      = (const float*)d_in[13];
    const float* wm      = (const float*)d_in[14];
    const float* bm      = (const float*)d_in[15];

    int N = in_sizes[0] / 3;
    int E = in_sizes[3] / 2;

    prep_kernel<<<1, 256>>>(ws, sscale, sshift, wm, mscale, mshift, emb, aes, bs, bm);

    int smembytes = SM_FLOATS * (int)sizeof(float);
    cudaFuncSetAttribute((const void*)magpot_kernel,
                         cudaFuncAttributeMaxDynamicSharedMemorySize, smembytes);
    magpot_kernel<<<(N + 3) / 4, 128, smembytes>>>(pos, species, mag, eidx, shifts, rbc,
                                                   (float*)d_out, N, E);
}

// round 2
// speedup vs baseline: 1.0852x; 1.0852x over previous
#include <cuda_runtime.h>

#define RCUT 5.0f

// ---- shared memory layout (float offsets) ----
#define OFF_C4    0        // 684: chebyshev->phi coeffs, 9 pairs * 19 float4
#define OFF_WSE   684      // 80
#define OFF_WME   764      // 251 (pad 256)
#define OFF_WDA   1020     // 64  (dmi weights, float4-aligned copy)
#define OFF_WDB   1084     // 64  (dmi-mix weights)
#define OFF_ESPEC 1148     // 3
#define OFF_C0    1151     // 1
#define OFF_TUP   1152     // 36 (ints)
#define OFF_BUF   1200     // 4 warps * 2176 (32 rows * 68 floats, stride 17 f4)
#define OFF_S     9904     // 4 warps * 192
#define SM_FLOATS 10672    // 42688 bytes

__global__ __launch_bounds__(128, 5)
void magpot_kernel(const float* __restrict__ pos, const int* __restrict__ species,
                   const float* __restrict__ mag, const int* __restrict__ eidx,
                   const float* __restrict__ shifts, const float* __restrict__ rbc,
                   const float* __restrict__ emb,
                   const float* __restrict__ sshift, const float* __restrict__ sscale,
                   const float* __restrict__ mshift, const float* __restrict__ mscale,
                   const float* __restrict__ aes,
                   const float* __restrict__ ws, const float* __restrict__ bs,
                   const float* __restrict__ wm, const float* __restrict__ bm,
                   float* __restrict__ out, int N, int E) {
    extern __shared__ float sm[];
    int tid = threadIdx.x, lane = tid & 31, warp = tid >> 5;

    // ---------------- per-block init: coeffs, normalized weights, tables ----------------
    {
        const float4* rbc4 = (const float4*)rbc;
        float4* c4 = (float4*)sm;
        for (int t = tid; t < 144; t += 128) { int pr = t >> 4, q = t & 15; c4[pr*19 + q] = rbc4[pr*16 + q]; }
        for (int t = tid; t < 80;  t += 128) sm[OFF_WSE + t] = ws[16 + t] / sscale[t];
        for (int t = tid; t < 251; t += 128) sm[OFF_WME + t] = wm[16 + t] / mscale[t];
        for (int t = tid; t < 64;  t += 128) {
            sm[OFF_WDA + t] = wm[16 + 83  + t] / mscale[83  + t];
            sm[OFF_WDB + t] = wm[16 + 163 + t] / mscale[163 + t];
        }
        if (tid < 3) {
            float s = aes[tid];
            #pragma unroll
            for (int k = 0; k < 16; k++) s += emb[tid*16 + k] * (ws[k] + wm[k]);
            sm[OFF_ESPEC + tid] = s;
        }
        if (tid < 36) {
            int p = tid, a = 0;
            while (p >= 8 - a) { p -= 8 - a; a++; }
            ((int*)sm)[OFF_TUP + tid] = (a << 3) | (a + p);
        }
    }
    __syncthreads();
    if (warp == 0) {
        float c = 0.0f;
        for (int d = lane; d < 80;  d += 32) c += sshift[d] * sm[OFF_WSE + d];
        for (int d = lane; d < 251; d += 32) c += mshift[d] * sm[OFF_WME + d];
        #pragma unroll
        for (int o = 16; o > 0; o >>= 1) c += __shfl_xor_sync(0xffffffffu, c, o);
        if (lane == 0) sm[OFF_C0] = bs[0] + bm[0] - c;
    }
    __syncthreads();

    int atom = blockIdx.x * 4 + warp;
    if (atom >= N) return;

    float* buf = sm + OFF_BUF + warp * 2176;
    float* S   = sm + OFF_S   + warp * 192;

    // ---------------- edge phase: lane = edge ----------------
    int e = atom * 32 + lane;
    int j = eidx[E + e];
    float pix = pos[atom*3+0], piy = pos[atom*3+1], piz = pos[atom*3+2];
    float rx = pos[j*3+0] - pix + shifts[e*3+0];
    float ry = pos[j*3+1] - piy + shifts[e*3+1];
    float rz = pos[j*3+2] - piz + shifts[e*3+2];
    float d2 = rx*rx + ry*ry + rz*rz;
    float invd = (d2 >= 1e-16f) ? rsqrtf(d2) : 0.0f;
    float dist = d2 * invd;

    float fc = (dist < RCUT) ? (0.5f*__cosf(0.6283185307f*dist) + 0.5f) : 0.0f;
    float xc = 0.08f*d2 - 1.0f;   // 2*(d/Rc)^2 - 1
    float f[8];
    {
        float t0 = 1.0f, t1 = xc;
        f[0] = fc;
        f[1] = 0.5f*(t1 + 1.0f)*fc;
        #pragma unroll
        for (int n = 2; n < 8; n++) { float t2 = 2.0f*xc*t1 - t0; f[n] = 0.5f*(t2 + 1.0f)*fc; t0 = t1; t1 = t2; }
    }
    int spi  = species[atom];
    int pair = spi*3 + species[j];
    const float4* c4 = (const float4*)sm;
    float phi[8];
    #pragma unroll
    for (int n = 0; n < 8; n++) {
        float4 a = c4[pair*19 + n*2], b = c4[pair*19 + n*2 + 1];
        phi[n] = a.x*f[0] + a.y*f[1] + a.z*f[2] + a.w*f[3]
               + b.x*f[4] + b.y*f[5] + b.z*f[6] + b.w*f[7];
    }
    float hx = rx*invd, hy = ry*invd, hz = rz*invd;
    float mjx = mag[j*3+0], mjy = mag[j*3+1], mjz = mag[j*3+2];
    float uj = mjx*mjx + mjy*mjy + mjz*mjz;
    float im = (uj >= 1e-16f) ? rsqrtf(uj) : 0.0f;
    float mdjx = mjx*im, mdjy = mjy*im, mdjz = mjz*im;
    const float THIRD = 1.0f/3.0f;

    float gv[17];
    gv[0]  = 1.0f;
    gv[1]  = hx;          gv[2]  = hy;          gv[3]  = hz;
    gv[4]  = hx*hx-THIRD; gv[5]  = hy*hy-THIRD; gv[6]  = hz*hz-THIRD;
    gv[7]  = hx*hy;       gv[8]  = hx*hz;       gv[9]  = hy*hz;
    gv[10] = mdjx;        gv[11] = mdjy;        gv[12] = mdjz;
    gv[13] = uj;
    gv[14] = uj*mdjx;     gv[15] = uj*mdjy;     gv[16] = uj*mdjz;

    // ---------------- staged outer-product reduction: S[k*8+n] = sum_e phi_n * g_k ----------
    // 3 rounds of up to 16 float4 groups; group G=2k+h holds phi[4h..4h+3]*g_k.
    float4* myrow = (float4*)(buf + lane * 68);     // stride 17 float4: conflict-free
    float4* S4 = (float4*)S;
    int col = lane & 15, half = lane >> 4;
    const float* rbase = buf + (half * 16) * 68 + col * 4;

    #pragma unroll
    for (int r = 0; r < 3; r++) {
        const int base = r * 16;
        const int cnt = (r == 2) ? 2 : 16;
        #pragma unroll
        for (int c = 0; c < cnt; c++) {
            int G = base + c, k = G >> 1, h = (G & 1) * 4;
            myrow[c] = make_float4(phi[h]*gv[k], phi[h+1]*gv[k], phi[h+2]*gv[k], phi[h+3]*gv[k]);
        }
        __syncwarp();
        float ax = 0.f, ay = 0.f, az = 0.f, aw = 0.f;
        #pragma unroll
        for (int i = 0; i < 16; i++) {
            const float4 v = *(const float4*)(rbase + i * 68);
            ax += v.x; ay += v.y; az += v.z; aw += v.w;
        }
        ax += __shfl_down_sync(0xffffffffu, ax, 16);
        ay += __shfl_down_sync(0xffffffffu, ay, 16);
        az += __shfl_down_sync(0xffffffffu, az, 16);
        aw += __shfl_down_sync(0xffffffffu, aw, 16);
        if (half == 0 && col < cnt) S4[base + col] = make_float4(ax, ay, az, aw);
        __syncwarp();
    }
    // S layout: S[n]=sum phi | S[8+8c+n]=P | S[32+8q+n]=Q6 | S[80+8c+n]=M |
    //           S[104+n]=namp | S[112+8c+n]=W

    // ---------------- atom phase ----------------
    float mx = mag[atom*3+0], my = mag[atom*3+1], mz = mag[atom*3+2];
    float u = mx*mx + my*my + mz*mz;
    float imi = (u >= 1e-16f) ? rsqrtf(u) : 0.0f;
    float mdx = mx*imi, mdy = my*imi, mdz = mz*imi;

    if (lane < 24) {
        int n = lane / 3, c = lane - n*3;
        int i0 = (c==0) ? 0 : (c+2);
        int i1 = (c==1) ? 1 : (c+3);
        int i2 = (c==2) ? 2 : (c+4);
        S[136 + lane] = S[32+8*i0+n]*mdx + S[32+8*i1+n]*mdy + S[32+8*i2+n]*mdz;  // mQ[n][c]
        int c1 = (c==2) ? 0 : c+1;
        int c2 = (c==0) ? 2 : c-1;
        float md1 = (c1==0) ? mdx : ((c1==1) ? mdy : mdz);
        float md2 = (c2==0) ? mdx : ((c2==1) ? mdy : mdz);
        S[160 + lane] = md1*S[80+8*c2+n] - md2*S[80+8*c1+n];                     // cc[n][c]
    }
    __syncwarp();

    float e_acc = (lane == 0) ? (sm[OFF_C0] + sm[OFF_ESPEC + spi]) : 0.0f;
    const int* TUP = ((const int*)sm) + OFF_TUP;

    // struct: radial(8) + PP triu(36) + QQ triu(36)
    for (int d = lane; d < 80; d += 32) {
        float val;
        if (d < 8) {
            val = S[d];
        } else if (d < 44) {
            int ab = TUP[d-8]; int a = ab >> 3, b = ab & 7;
            val = S[8+a]*S[8+b] + S[16+a]*S[16+b] + S[24+a]*S[24+b];
        } else {
            int ab = TUP[d-44]; int a = ab >> 3, b = ab & 7;
            val = S[32+a]*S[32+b] + S[40+a]*S[40+b] + S[48+a]*S[48+b]
                + 2.0f*(S[56+a]*S[56+b] + S[64+a]*S[64+b] + S[72+a]*S[72+b]);
        }
        e_acc += val * sm[OFF_WSE + d];
    }

    // mag (amp, iso, sia, sae, nbr_amp, nbr_ex; u-mix weights folded)
    for (int t = lane; t < 99; t += 32) {
        int f2 = (t < 83) ? t : t + 144;
        float val, wt;
        if (f2 < 3) {
            val = (f2 == 0) ? u : ((f2 == 1) ? u*u : u*u*u);
            wt = sm[OFF_WME + f2];
        } else if (f2 < 11) {
            int n = f2 - 3;
            val = mdx*S[80+n] + mdy*S[88+n] + mdz*S[96+n];
            wt = sm[OFF_WME + f2] + u*sm[OFF_WME + 147 + n];
        } else if (f2 < 19) {
            int n = f2 - 11;
            val = mdx*S[136+n*3] + mdy*S[136+n*3+1] + mdz*S[136+n*3+2];
            wt = sm[OFF_WME + f2] + u*sm[OFF_WME + 155 + n];
        } else if (f2 < 83) {
            int p = f2 - 19; int m = p >> 3, n2 = p & 7;
            val = S[136+m*3]*S[80+n2] + S[136+m*3+1]*S[88+n2] + S[136+m*3+2]*S[96+n2];
            wt = sm[OFF_WME + f2];
        } else if (f2 < 235) {
            int n = f2 - 227;
            val = S[104+n];
            wt = sm[OFF_WME + f2];
        } else {
            int n = f2 - 235;
            val = mdx*S[112+n] + mdy*S[120+n] + mdz*S[128+n];
            wt = sm[OFF_WME + f2] + u*sm[OFF_WME + 243 + n];
        }
        e_acc += val * wt;
    }

    // ---------------- DMI: fused exclusive-prefix-scan + contraction ----------------
    float ccx[8], ccy[8], ccz[8];
    #pragma unroll
    for (int m = 0; m < 8; m++) {
        ccx[m] = S[160+m*3]; ccy[m] = S[160+m*3+1]; ccz[m] = S[160+m*3+2];
    }
    const float4* wdA4 = (const float4*)(sm + OFF_WDA);
    const float4* wdB4 = (const float4*)(sm + OFF_WDB);
    #pragma unroll
    for (int n = 0; n < 8; n++) {
        float vx = phi[n]*rx, vy = phi[n]*ry, vz = phi[n]*rz;
        float sx = vx, sy = vy, sz = vz;
        #pragma unroll
        for (int o = 1; o < 32; o <<= 1) {
            float tx = __shfl_up_sync(0xffffffffu, sx, o);
            float ty = __shfl_up_sync(0xffffffffu, sy, o);
            float tz = __shfl_up_sync(0xffffffffu, sz, o);
            if (lane >= o) { sx += tx; sy += ty; sz += tz; }
        }
        sx -= vx; sy -= vy; sz -= vz;   // exclusive prefix of phi_n * r
        float4 a0 = wdA4[2*n], a1 = wdA4[2*n+1];
        float4 b0 = wdB4[2*n], b1 = wdB4[2*n+1];
        float tnx = 0.f, tny = 0.f, tnz = 0.f, s;
        s = phi[0]*(a0.x + u*b0.x); tnx += s*ccx[0]; tny += s*ccy[0]; tnz += s*ccz[0];
        s = phi[1]*(a0.y + u*b0.y); tnx += s*ccx[1]; tny += s*ccy[1]; tnz += s*ccz[1];
        s = phi[2]*(a0.z + u*b0.z); tnx += s*ccx[2]; tny += s*ccy[2]; tnz += s*ccz[2];
        s = phi[3]*(a0.w + u*b0.w); tnx += s*ccx[3]; tny += s*ccy[3]; tnz += s*ccz[3];
        s = phi[4]*(a1.x + u*b1.x); tnx += s*ccx[4]; tny += s*ccy[4]; tnz += s*ccz[4];
        s = phi[5]*(a1.y + u*b1.y); tnx += s*ccx[5]; tny += s*ccy[5]; tnz += s*ccz[5];
        s = phi[6]*(a1.z + u*b1.z); tnx += s*ccx[6]; tny += s*ccy[6]; tnz += s*ccz[6];
        s = phi[7]*(a1.w + u*b1.w); tnx += s*ccx[7]; tny += s*ccy[7]; tnz += s*ccz[7];
        float qx = ry*tnz - rz*tny;
        float qy = rz*tnx - rx*tnz;
        float qz = rx*tny - ry*tnx;
        e_acc += sx*qx + sy*qy + sz*qz;
    }

    #pragma unroll
    for (int o = 16; o > 0; o >>= 1) e_acc += __shfl_xor_sync(0xffffffffu, e_acc, o);
    if (lane == 0) out[atom] = e_acc;
}

extern "C" void kernel_launch(void* const* d_in, const int* in_sizes, int n_in,
                              void* d_out, int out_size) {
    const float* pos     = (const float*)d_in[0];
    const int*   species = (const int*)  d_in[1];
    const float* mag     = (const float*)d_in[2];
    const int*   eidx    = (const int*)  d_in[3];
    const float* shifts  = (const float*)d_in[4];
    const float* rbc     = (const float*)d_in[5];
    const float* emb     = (const float*)d_in[6];
    const float* sshift  = (const float*)d_in[7];
    const float* sscale  = (const float*)d_in[8];
    const float* mshift  = (const float*)d_in[9];
    const float* mscale  = (const float*)d_in[10];
    const float* aes     = (const float*)d_in[11];
    const float* ws      = (const float*)d_in[12];
    const float* bs      = (const float*)d_in[13];
    const float* wm      = (const float*)d_in[14];
    const float* bm      = (const float*)d_in[15];

    int N = in_sizes[0] / 3;
    int E = in_sizes[3] / 2;

    int smembytes = SM_FLOATS * (int)sizeof(float);
    cudaFuncSetAttribute((const void*)magpot_kernel,
                         cudaFuncAttributeMaxDynamicSharedMemorySize, smembytes);
    magpot_kernel<<<(N + 3) / 4, 128, smembytes>>>(pos, species, mag, eidx, shifts, rbc,
                                                   emb, sshift, sscale, mshift, mscale, aes,
                                                   ws, bs, wm, bm, (float*)d_out, N, E);
}

// round 3
// speedup vs baseline: 1.3689x; 1.2614x over previous
#include <cuda_runtime.h>

#define RCUT 5.0f

// ---- shared memory layout (float offsets) ----
#define OFF_C4    0        // 684: chebyshev->phi coeffs, 9 pairs * 19 float4
#define OFF_WSE   684      // 80
#define OFF_WME   764      // 251 (pad 256)
#define OFF_WDA   1020     // 64  dmi weights
#define OFF_WDB   1084     // 64  dmi-mix weights
#define OFF_ESPEC 1148     // 3
#define OFF_C0    1151     // 1
#define OFF_TUP   1152     // 36 ints (pad to 1188)
#define OFF_BUF   1188     // 4 warps * 1152 (32 rows * 36 floats; row = 9 float4)
#define OFF_S     5796     // 4 warps * 160
#define SM_FLOATS 6436     // 25744 bytes

__global__ __launch_bounds__(128, 6)
void magpot_kernel(const float* __restrict__ pos, const int* __restrict__ species,
                   const float* __restrict__ mag, const int* __restrict__ eidx,
                   const float* __restrict__ shifts, const float* __restrict__ rbc,
                   const float* __restrict__ emb,
                   const float* __restrict__ sshift, const float* __restrict__ sscale,
                   const float* __restrict__ mshift, const float* __restrict__ mscale,
                   const float* __restrict__ aes,
                   const float* __restrict__ ws, const float* __restrict__ bs,
                   const float* __restrict__ wm, const float* __restrict__ bm,
                   float* __restrict__ out, int N, int E) {
    extern __shared__ float sm[];
    int tid = threadIdx.x, lane = tid & 31, warp = tid >> 5;

    // ---------------- per-block init ----------------
    {
        const float4* rbc4 = (const float4*)rbc;
        float4* c4w = (float4*)sm;
        for (int t = tid; t < 144; t += 128) { int pr = t >> 4, q = t & 15; c4w[pr*19 + q] = rbc4[pr*16 + q]; }
        for (int t = tid; t < 80;  t += 128) sm[OFF_WSE + t] = ws[16 + t] / sscale[t];
        for (int t = tid; t < 251; t += 128) sm[OFF_WME + t] = wm[16 + t] / mscale[t];
        for (int t = tid; t < 64;  t += 128) {
            sm[OFF_WDA + t] = wm[16 + 83  + t] / mscale[83  + t];
            sm[OFF_WDB + t] = wm[16 + 163 + t] / mscale[163 + t];
        }
        if (tid < 3) {
            float s = aes[tid];
            #pragma unroll
            for (int k = 0; k < 16; k++) s += emb[tid*16 + k] * (ws[k] + wm[k]);
            sm[OFF_ESPEC + tid] = s;
        }
        if (tid < 36) {
            int p = tid, a = 0;
            while (p >= 8 - a) { p -= 8 - a; a++; }
            ((int*)sm)[OFF_TUP + tid] = (a << 3) | (a + p);
        }
    }
    __syncthreads();
    if (warp == 0) {
        float c = 0.0f;
        for (int d = lane; d < 80;  d += 32) c += sshift[d] * sm[OFF_WSE + d];
        for (int d = lane; d < 251; d += 32) c += mshift[d] * sm[OFF_WME + d];
        #pragma unroll
        for (int o = 16; o > 0; o >>= 1) c += __shfl_xor_sync(0xffffffffu, c, o);
        if (lane == 0) sm[OFF_C0] = bs[0] + bm[0] - c;
    }
    __syncthreads();

    int atom = blockIdx.x * 4 + warp;
    if (atom >= N) return;

    float* buf = sm + OFF_BUF + warp * 1152;
    float* S   = sm + OFF_S   + warp * 160;

    // ---------------- edge phase: lane = edge ----------------
    int e = atom * 32 + lane;
    int j = eidx[E + e];
    float pix = pos[atom*3+0], piy = pos[atom*3+1], piz = pos[atom*3+2];
    float rx = pos[j*3+0] - pix + shifts[e*3+0];
    float ry = pos[j*3+1] - piy + shifts[e*3+1];
    float rz = pos[j*3+2] - piz + shifts[e*3+2];
    float d2 = rx*rx + ry*ry + rz*rz;
    float invd = (d2 >= 1e-16f) ? rsqrtf(d2) : 0.0f;
    float dist = d2 * invd;

    float fc = (dist < RCUT) ? (0.5f*__cosf(0.6283185307f*dist) + 0.5f) : 0.0f;
    float xc = 0.08f*d2 - 1.0f;
    float f[8];
    {
        float t0 = 1.0f, t1 = xc;
        f[0] = fc;
        f[1] = 0.5f*(t1 + 1.0f)*fc;
        #pragma unroll
        for (int n = 2; n < 8; n++) { float t2 = 2.0f*xc*t1 - t0; f[n] = 0.5f*(t2 + 1.0f)*fc; t0 = t1; t1 = t2; }
    }
    int spi  = species[atom];
    int pair = spi*3 + species[j];
    const float4* c4 = (const float4*)sm;
    float phi[8];
    #pragma unroll
    for (int n = 0; n < 8; n++) {
        float4 a = c4[pair*19 + n*2], b = c4[pair*19 + n*2 + 1];
        phi[n] = a.x*f[0] + a.y*f[1] + a.z*f[2] + a.w*f[3]
               + b.x*f[4] + b.y*f[5] + b.z*f[6] + b.w*f[7];
    }
    float hx = rx*invd, hy = ry*invd, hz = rz*invd;
    float mjx = mag[j*3+0], mjy = mag[j*3+1], mjz = mag[j*3+2];
    float uj = mjx*mjx + mjy*mjy + mjz*mjz;
    float im = (uj >= 1e-16f) ? rsqrtf(uj) : 0.0f;
    float mdjx = mjx*im, mdjy = mjy*im, mdjz = mjz*im;
    const float THIRD = 1.0f/3.0f;

    // atom-level magnetics (hoisted for the linear fold)
    float mx = mag[atom*3+0], my = mag[atom*3+1], mz = mag[atom*3+2];
    float u = mx*mx + my*my + mz*mz;
    float imi = (u >= 1e-16f) ? rsqrtf(u) : 0.0f;
    float mdx = mx*imi, mdy = my*imi, mdz = mz*imi;

    // per-edge fold of descriptors linear in segment sums
    float dotmm = mdx*mdjx + mdy*mdjy + mdz*mdjz;
    float dmh   = mdx*hx + mdy*hy + mdz*hz;
    float mm2   = mdx*mdx + mdy*mdy + mdz*mdz;
    float tq    = dmh*dmh - THIRD*mm2;
    float e_acc = 0.0f;
    #pragma unroll
    for (int n = 0; n < 8; n++) {
        float A = sm[OFF_WSE + n];
        float B = sm[OFF_WME + 3   + n] + u*sm[OFF_WME + 147 + n];
        float C = sm[OFF_WME + 11  + n] + u*sm[OFF_WME + 155 + n];
        float D = sm[OFF_WME + 227 + n];
        float Ew = sm[OFF_WME + 235 + n] + u*sm[OFF_WME + 243 + n];
        e_acc += phi[n]*(A + B*dotmm + C*tq + uj*(D + Ew*dotmm));
    }

    float gv[12];
    gv[0] = hx;          gv[1]  = hy;          gv[2]  = hz;
    gv[3] = hx*hx-THIRD; gv[4]  = hy*hy-THIRD; gv[5]  = hz*hz-THIRD;
    gv[6] = hx*hy;       gv[7]  = hx*hz;       gv[8]  = hy*hz;
    gv[9] = mdjx;        gv[10] = mdjy;        gv[11] = mdjz;

    // ---------------- quarter-split outer-product reduction ----------------
    // 24 float4 groups: G = 2k+h holds phi[4h..4h+3]*gv[k]. 3 rounds x 8 cols.
    // S[8k+n] = sum_e phi_n * gv_k : P@0, Q6@24, M@72
    float4* myrow = (float4*)(buf + lane * 36);          // 9-float4 row stride
    float4* S4 = (float4*)S;
    int col = lane & 7, rg = lane >> 3;
    const float* rbase = buf + (rg * 8) * 36 + col * 4;

    #pragma unroll
    for (int r = 0; r < 3; r++) {
        #pragma unroll
        for (int c = 0; c < 8; c++) {
            int G = r*8 + c, k = G >> 1, h = (G & 1) * 4;
            float g = gv[k];
            myrow[c] = make_float4(phi[h]*g, phi[h+1]*g, phi[h+2]*g, phi[h+3]*g);
        }
        __syncwarp();
        float ax = 0.f, ay = 0.f, az = 0.f, aw = 0.f;
        #pragma unroll
        for (int i = 0; i < 8; i++) {
            const float4 v = *(const float4*)(rbase + i * 36);
            ax += v.x; ay += v.y; az += v.z; aw += v.w;
        }
        ax += __shfl_xor_sync(0xffffffffu, ax, 8);
        ay += __shfl_xor_sync(0xffffffffu, ay, 8);
        az += __shfl_xor_sync(0xffffffffu, az, 8);
        aw += __shfl_xor_sync(0xffffffffu, aw, 8);
        ax += __shfl_xor_sync(0xffffffffu, ax, 16);
        ay += __shfl_xor_sync(0xffffffffu, ay, 16);
        az += __shfl_xor_sync(0xffffffffu, az, 16);
        aw += __shfl_xor_sync(0xffffffffu, aw, 16);
        if (lane < 8) S4[r*8 + lane] = make_float4(ax, ay, az, aw);
        __syncwarp();
    }

    // ---------------- atom phase ----------------
    // mQ[n][c] -> S[96+n*3+c], cc[n][c] -> S[120+n*3+c]
    if (lane < 24) {
        int n = lane / 3, c = lane - n*3;
        int i0 = (c==0) ? 0 : (c+2);
        int i1 = (c==1) ? 1 : (c+3);
        int i2 = (c==2) ? 2 : (c+4);
        S[96 + lane] = S[24+8*i0+n]*mdx + S[24+8*i1+n]*mdy + S[24+8*i2+n]*mdz;
        int c1 = (c==2) ? 0 : c+1;
        int c2 = (c==0) ? 2 : c-1;
        float md1 = (c1==0) ? mdx : ((c1==1) ? mdy : mdz);
        float md2 = (c2==0) ? mdx : ((c2==1) ? mdy : mdz);
        S[120 + lane] = md1*S[72+8*c2+n] - md2*S[72+8*c1+n];
    }
    __syncwarp();

    if (lane == 0) {
        e_acc += sm[OFF_C0] + sm[OFF_ESPEC + spi]
               + u*(sm[OFF_WME] + u*(sm[OFF_WME+1] + u*sm[OFF_WME+2]));
    }
    const int* TUP = ((const int*)sm) + OFF_TUP;

    // struct bilinear: PP triu(36) + QQ triu(36)
    for (int d = lane; d < 72; d += 32) {
        float val;
        if (d < 36) {
            int ab = TUP[d]; int a = ab >> 3, b = ab & 7;
            val = S[a]*S[b] + S[8+a]*S[8+b] + S[16+a]*S[16+b];
        } else {
            int ab = TUP[d-36]; int a = ab >> 3, b = ab & 7;
            val = S[24+a]*S[24+b] + S[32+a]*S[32+b] + S[40+a]*S[40+b]
                + 2.0f*(S[48+a]*S[48+b] + S[56+a]*S[56+b] + S[64+a]*S[64+b]);
        }
        e_acc += val * sm[OFF_WSE + 8 + d];
    }

    // sae(64): exactly 2 iterations
    for (int t = lane; t < 64; t += 32) {
        int m = t >> 3, n2 = t & 7;
        float val = S[96+m*3]*S[72+n2] + S[96+m*3+1]*S[80+n2] + S[96+m*3+2]*S[88+n2];
        e_acc += val * sm[OFF_WME + 19 + t];
    }

    // ---------------- DMI: exclusive-prefix-scan + contraction ----------------
    float ccx[8], ccy[8], ccz[8];
    #pragma unroll
    for (int m = 0; m < 8; m++) {
        ccx[m] = S[120+m*3]; ccy[m] = S[120+m*3+1]; ccz[m] = S[120+m*3+2];
    }
    const float4* wdA4 = (const float4*)(sm + OFF_WDA);
    const float4* wdB4 = (const float4*)(sm + OFF_WDB);
    #pragma unroll
    for (int n = 0; n < 8; n++) {
        float vx = phi[n]*rx, vy = phi[n]*ry, vz = phi[n]*rz;
        float sx = vx, sy = vy, sz = vz;
        #pragma unroll
        for (int o = 1; o < 32; o <<= 1) {
            float tx = __shfl_up_sync(0xffffffffu, sx, o);
            float ty = __shfl_up_sync(0xffffffffu, sy, o);
            float tz = __shfl_up_sync(0xffffffffu, sz, o);
            if (lane >= o) { sx += tx; sy += ty; sz += tz; }
        }
        sx -= vx; sy -= vy; sz -= vz;
        float4 a0 = wdA4[2*n], a1 = wdA4[2*n+1];
        float4 b0 = wdB4[2*n], b1 = wdB4[2*n+1];
        float tnx = 0.f, tny = 0.f, tnz = 0.f, s;
        s = phi[0]*(a0.x + u*b0.x); tnx += s*ccx[0]; tny += s*ccy[0]; tnz += s*ccz[0];
        s = phi[1]*(a0.y + u*b0.y); tnx += s*ccx[1]; tny += s*ccy[1]; tnz += s*ccz[1];
        s = phi[2]*(a0.z + u*b0.z); tnx += s*ccx[2]; tny += s*ccy[2]; tnz += s*ccz[2];
        s = phi[3]*(a0.w + u*b0.w); tnx += s*ccx[3]; tny += s*ccy[3]; tnz += s*ccz[3];
        s = phi[4]*(a1.x + u*b1.x); tnx += s*ccx[4]; tny += s*ccy[4]; tnz += s*ccz[4];
        s = phi[5]*(a1.y + u*b1.y); tnx += s*ccx[5]; tny += s*ccy[5]; tnz += s*ccz[5];
        s = phi[6]*(a1.z + u*b1.z); tnx += s*ccx[6]; tny += s*ccy[6]; tnz += s*ccz[6];
        s = phi[7]*(a1.w + u*b1.w); tnx += s*ccx[7]; tny += s*ccy[7]; tnz += s*ccz[7];
        float qx = ry*tnz - rz*tny;
        float qy = rz*tnx - rx*tnz;
        float qz = rx*tny - ry*tnx;
        e_acc += sx*qx + sy*qy + sz*qz;
    }

    #pragma unroll
    for (int o = 16; o > 0; o >>= 1) e_acc += __shfl_xor_sync(0xffffffffu, e_acc, o);
    if (lane == 0) out[atom] = e_acc;
}

extern "C" void kernel_launch(void* const* d_in, const int* in_sizes, int n_in,
                              void* d_out, int out_size) {
    const float* pos     = (const float*)d_in[0];
    const int*   species = (const int*)  d_in[1];
    const float* mag     = (const float*)d_in[2];
    const int*   eidx    = (const int*)  d_in[3];
    const float* shifts  = (const float*)d_in[4];
    const float* rbc     = (const float*)d_in[5];
    const float* emb     = (const float*)d_in[6];
    const float* sshift  = (const float*)d_in[7];
    const float* sscale  = (const float*)d_in[8];
    const float* mshift  = (const float*)d_in[9];
    const float* mscale  = (const float*)d_in[10];
    const float* aes     = (const float*)d_in[11];
    const float* ws      = (const float*)d_in[12];
    const float* bs      = (const float*)d_in[13];
    const float* wm      = (const float*)d_in[14];
    const float* bm      = (const float*)d_in[15];

    int N = in_sizes[0] / 3;
    int E = in_sizes[3] / 2;

    int smembytes = SM_FLOATS * (int)sizeof(float);
    cudaFuncSetAttribute((const void*)magpot_kernel,
                         cudaFuncAttributeMaxDynamicSharedMemorySize, smembytes);
    magpot_kernel<<<(N + 3) / 4, 128, smembytes>>>(pos, species, mag, eidx, shifts, rbc,
                                                   emb, sshift, sscale, mshift, mscale, aes,
                                                   ws, bs, wm, bm, (float*)d_out, N, E);
}

// round 4
// speedup vs baseline: 1.4513x; 1.0602x over previous
#include <cuda_runtime.h>

#define RCUT 5.0f
#define MAXN 65536

// ---- device-global precomputed state (written by prep kernel each launch) ----
__device__ float4 g_pack[2*MAXN];   // per atom: [pos.x,pos.y,pos.z,species_bits],[mdir.x,y,z,u]
__device__ float  g_wse[80];        // struct weights / scale
__device__ float  g_wme[256];       // mag weights / scale (amp + sae used directly)
__device__ float4 g_fold[16];       // 8 families x 2 float4 (per-edge linear fold weights)
__device__ float4 g_wdA[16];        // dmi weights
__device__ float4 g_wdB[16];        // dmi-mix weights
__device__ float  g_espec[3];
__device__ float  g_c0;
__device__ int    g_tup[36];

__global__ void prep_kernel(const float* __restrict__ pos, const int* __restrict__ species,
                            const float* __restrict__ mag,
                            const float* __restrict__ emb,
                            const float* __restrict__ sshift, const float* __restrict__ sscale,
                            const float* __restrict__ mshift, const float* __restrict__ mscale,
                            const float* __restrict__ aes,
                            const float* __restrict__ ws, const float* __restrict__ bs,
                            const float* __restrict__ wm, const float* __restrict__ bm,
                            int N) {
    int idx = blockIdx.x * 256 + threadIdx.x;
    if (idx < N) {
        float px = pos[idx*3+0], py = pos[idx*3+1], pz = pos[idx*3+2];
        float mx = mag[idx*3+0], my = mag[idx*3+1], mz = mag[idx*3+2];
        float u = mx*mx + my*my + mz*mz;
        float im = (u >= 1e-16f) ? rsqrtf(u) : 0.0f;
        g_pack[2*idx]   = make_float4(px, py, pz, __int_as_float(species[idx]));
        g_pack[2*idx+1] = make_float4(mx*im, my*im, mz*im, u);
    }
    if (blockIdx.x == 0) {
        int t = threadIdx.x;
        for (int d = t; d < 80;  d += 256) g_wse[d] = ws[16 + d] / sscale[d];
        for (int d = t; d < 251; d += 256) g_wme[d] = wm[16 + d] / mscale[d];
        if (t < 64) {
            ((float*)g_wdA)[t] = wm[16 + 83  + t] / mscale[83  + t];
            ((float*)g_wdB)[t] = wm[16 + 163 + t] / mscale[163 + t];
        }
        if (t < 64) {
            // fold families: 0:struct-radial 1:iso 2:sia 3:nbr_amp 4:nbr_ex 5:iso-mix 6:sia-mix 7:nbr_ex-mix
            const int foff[8] = {0, 3, 11, 227, 235, 147, 155, 243};
            int fam = t >> 3, k = t & 7;
            float v;
            if (fam == 0) v = ws[16 + k] / sscale[k];
            else          v = wm[16 + foff[fam] + k] / mscale[foff[fam] + k];
            ((float*)g_fold)[t] = v;
        }
        if (t < 3) {
            float s = aes[t];
            #pragma unroll
            for (int k = 0; k < 16; k++) s += emb[t*16 + k] * (ws[k] + wm[k]);
            g_espec[t] = s;
        }
        if (t < 36) {
            int p = t, a = 0;
            while (p >= 8 - a) { p -= 8 - a; a++; }
            g_tup[t] = (a << 3) | (a + p);
        }
        if (t < 32) {
            float c = 0.0f;
            for (int d = t; d < 80;  d += 32) c += sshift[d] * ws[16 + d] / sscale[d];
            for (int d = t; d < 251; d += 32) c += mshift[d] * wm[16 + d] / mscale[d];
            #pragma unroll
            for (int o = 16; o > 0; o >>= 1) c += __shfl_xor_sync(0xffffffffu, c, o);
            if (t == 0) g_c0 = bs[0] + bm[0] - c;
        }
    }
}

// smem: per warp 1312 floats = staging buf (32 rows * 36 floats) + S (160)
#define WARP_SM 1312
#define SM_FLOATS (4 * WARP_SM)

__global__ __launch_bounds__(128, 7)
void magpot_kernel(const float* __restrict__ eidx_j, const float* __restrict__ shifts,
                   const float* __restrict__ rbc,
                   float* __restrict__ out, int N) {
    extern __shared__ float smw[];
    int lane = threadIdx.x & 31, warp = threadIdx.x >> 5;
    int atom = blockIdx.x * 4 + warp;
    if (atom >= N) return;

    float* buf = smw + warp * WARP_SM;
    float* S   = buf + 1152;

    // ---------------- edge phase: lane = edge ----------------
    int e = atom * 32 + lane;
    int j = ((const int*)eidx_j)[e];

    float4 ak0 = __ldg(&g_pack[2*atom]);
    float4 ak1 = __ldg(&g_pack[2*atom+1]);
    float4 pk0 = __ldg(&g_pack[2*j]);
    float4 pk1 = __ldg(&g_pack[2*j+1]);

    float rx = pk0.x - ak0.x + shifts[e*3+0];
    float ry = pk0.y - ak0.y + shifts[e*3+1];
    float rz = pk0.z - ak0.z + shifts[e*3+2];
    float d2 = rx*rx + ry*ry + rz*rz;
    float invd = (d2 >= 1e-16f) ? rsqrtf(d2) : 0.0f;
    float dist = d2 * invd;

    float fc = (dist < RCUT) ? (0.5f*__cosf(0.6283185307f*dist) + 0.5f) : 0.0f;
    float xc = 0.08f*d2 - 1.0f;
    float f[8];
    {
        float t0 = 1.0f, t1 = xc;
        f[0] = fc;
        f[1] = 0.5f*(t1 + 1.0f)*fc;
        #pragma unroll
        for (int n = 2; n < 8; n++) { float t2 = 2.0f*xc*t1 - t0; f[n] = 0.5f*(t2 + 1.0f)*fc; t0 = t1; t1 = t2; }
    }
    int spi  = __float_as_int(ak0.w);
    int pair = spi*3 + __float_as_int(pk0.w);
    const float4* c4 = (const float4*)rbc;
    float phi[8];
    #pragma unroll
    for (int n = 0; n < 8; n++) {
        float4 a = __ldg(&c4[pair*16 + n*2]), b = __ldg(&c4[pair*16 + n*2 + 1]);
        phi[n] = a.x*f[0] + a.y*f[1] + a.z*f[2] + a.w*f[3]
               + b.x*f[4] + b.y*f[5] + b.z*f[6] + b.w*f[7];
    }
    float hx = rx*invd, hy = ry*invd, hz = rz*invd;
    float mdjx = pk1.x, mdjy = pk1.y, mdjz = pk1.z, uj = pk1.w;
    float mdx = ak1.x, mdy = ak1.y, mdz = ak1.z, u = ak1.w;
    const float THIRD = 1.0f/3.0f;

    // per-edge fold of descriptors linear in segment sums
    float dotmm = mdx*mdjx + mdy*mdjy + mdz*mdjz;
    float dmh   = mdx*hx + mdy*hy + mdz*hz;
    float mm2   = mdx*mdx + mdy*mdy + mdz*mdz;
    float tq    = dmh*dmh - THIRD*mm2;
    float e_acc = 0.0f;
    #pragma unroll
    for (int h = 0; h < 2; h++) {
        float4 A  = __ldg(&g_fold[0  + h]);
        float4 B0 = __ldg(&g_fold[2  + h]);
        float4 C0 = __ldg(&g_fold[4  + h]);
        float4 D  = __ldg(&g_fold[6  + h]);
        float4 E0 = __ldg(&g_fold[8  + h]);
        float4 Bu = __ldg(&g_fold[10 + h]);
        float4 Cu = __ldg(&g_fold[12 + h]);
        float4 Eu = __ldg(&g_fold[14 + h]);
        e_acc += phi[4*h+0]*(A.x + (B0.x+u*Bu.x)*dotmm + (C0.x+u*Cu.x)*tq + uj*(D.x + (E0.x+u*Eu.x)*dotmm));
        e_acc += phi[4*h+1]*(A.y + (B0.y+u*Bu.y)*dotmm + (C0.y+u*Cu.y)*tq + uj*(D.y + (E0.y+u*Eu.y)*dotmm));
        e_acc += phi[4*h+2]*(A.z + (B0.z+u*Bu.z)*dotmm + (C0.z+u*Cu.z)*tq + uj*(D.z + (E0.z+u*Eu.z)*dotmm));
        e_acc += phi[4*h+3]*(A.w + (B0.w+u*Bu.w)*dotmm + (C0.w+u*Cu.w)*tq + uj*(D.w + (E0.w+u*Eu.w)*dotmm));
    }

    float gv[12];
    gv[0] = hx;          gv[1]  = hy;          gv[2]  = hz;
    gv[3] = hx*hx-THIRD; gv[4]  = hy*hy-THIRD; gv[5]  = hz*hz-THIRD;
    gv[6] = hx*hy;       gv[7]  = hx*hz;       gv[8]  = hy*hz;
    gv[9] = mdjx;        gv[10] = mdjy;        gv[11] = mdjz;

    // ---------------- quarter-split outer-product reduction ----------------
    // S[8k+n] = sum_e phi_n * gv_k : P@0, Q6@24, M@72
    float4* myrow = (float4*)(buf + lane * 36);
    float4* S4 = (float4*)S;
    int col = lane & 7, rg = lane >> 3;
    const float* rbase = buf + (rg * 8) * 36 + col * 4;

    #pragma unroll
    for (int r = 0; r < 3; r++) {
        #pragma unroll
        for (int c = 0; c < 8; c++) {
            int G = r*8 + c, k = G >> 1, h2 = (G & 1) * 4;
            float g = gv[k];
            myrow[c] = make_float4(phi[h2]*g, phi[h2+1]*g, phi[h2+2]*g, phi[h2+3]*g);
        }
        __syncwarp();
        float ax = 0.f, ay = 0.f, az = 0.f, aw = 0.f;
        #pragma unroll
        for (int i = 0; i < 8; i++) {
            const float4 v = *(const float4*)(rbase + i * 36);
            ax += v.x; ay += v.y; az += v.z; aw += v.w;
        }
        ax += __shfl_xor_sync(0xffffffffu, ax, 8);
        ay += __shfl_xor_sync(0xffffffffu, ay, 8);
        az += __shfl_xor_sync(0xffffffffu, az, 8);
        aw += __shfl_xor_sync(0xffffffffu, aw, 8);
        ax += __shfl_xor_sync(0xffffffffu, ax, 16);
        ay += __shfl_xor_sync(0xffffffffu, ay, 16);
        az += __shfl_xor_sync(0xffffffffu, az, 16);
        aw += __shfl_xor_sync(0xffffffffu, aw, 16);
        if (lane < 8) S4[r*8 + lane] = make_float4(ax, ay, az, aw);
        __syncwarp();
    }

    // ---------------- atom phase ----------------
    // mQ[n][c] -> S[96+n*3+c], cc[n][c] -> S[120+n*3+c]
    if (lane < 24) {
        int n = lane / 3, c = lane - n*3;
        int i0 = (c==0) ? 0 : (c+2);
        int i1 = (c==1) ? 1 : (c+3);
        int i2 = (c==2) ? 2 : (c+4);
        S[96 + lane] = S[24+8*i0+n]*mdx + S[24+8*i1+n]*mdy + S[24+8*i2+n]*mdz;
        int c1 = (c==2) ? 0 : c+1;
        int c2 = (c==0) ? 2 : c-1;
        float md1 = (c1==0) ? mdx : ((c1==1) ? mdy : mdz);
        float md2 = (c2==0) ? mdx : ((c2==1) ? mdy : mdz);
        S[120 + lane] = md1*S[72+8*c2+n] - md2*S[72+8*c1+n];
    }
    __syncwarp();

    if (lane == 0) {
        e_acc += __ldg(&g_c0) + __ldg(&g_espec[spi])
               + u*(__ldg(&g_wme[0]) + u*(__ldg(&g_wme[1]) + u*__ldg(&g_wme[2])));
    }

    // struct bilinear: PP triu(36) + QQ triu(36)
    for (int d = lane; d < 72; d += 32) {
        float val;
        if (d < 36) {
            int ab = __ldg(&g_tup[d]); int a = ab >> 3, b = ab & 7;
            val = S[a]*S[b] + S[8+a]*S[8+b] + S[16+a]*S[16+b];
        } else {
            int ab = __ldg(&g_tup[d-36]); int a = ab >> 3, b = ab & 7;
            val = S[24+a]*S[24+b] + S[32+a]*S[32+b] + S[40+a]*S[40+b]
                + 2.0f*(S[48+a]*S[48+b] + S[56+a]*S[56+b] + S[64+a]*S[64+b]);
        }
        e_acc += val * __ldg(&g_wse[8 + d]);
    }

    // sae(64): exactly 2 iterations
    for (int t = lane; t < 64; t += 32) {
        int m = t >> 3, n2 = t & 7;
        float val = S[96+m*3]*S[72+n2] + S[96+m*3+1]*S[80+n2] + S[96+m*3+2]*S[88+n2];
        e_acc += val * __ldg(&g_wme[19 + t]);
    }

    // ---------------- DMI: exclusive-prefix-scan + contraction ----------------
    float ccx[8], ccy[8], ccz[8];
    #pragma unroll
    for (int m = 0; m < 8; m++) {
        ccx[m] = S[120+m*3]; ccy[m] = S[120+m*3+1]; ccz[m] = S[120+m*3+2];
    }
    #pragma unroll
    for (int n = 0; n < 8; n++) {
        float vx = phi[n]*rx, vy = phi[n]*ry, vz = phi[n]*rz;
        float sx = vx, sy = vy, sz = vz;
        #pragma unroll
        for (int o = 1; o < 32; o <<= 1) {
            float tx = __shfl_up_sync(0xffffffffu, sx, o);
            float ty = __shfl_up_sync(0xffffffffu, sy, o);
            float tz = __shfl_up_sync(0xffffffffu, sz, o);
            if (lane >= o) { sx += tx; sy += ty; sz += tz; }
        }
        sx -= vx; sy -= vy; sz -= vz;
        float4 a0 = __ldg(&g_wdA[2*n]), a1 = __ldg(&g_wdA[2*n+1]);
        float4 b0 = __ldg(&g_wdB[2*n]), b1 = __ldg(&g_wdB[2*n+1]);
        float tnx = 0.f, tny = 0.f, tnz = 0.f, s;
        s = phi[0]*(a0.x + u*b0.x); tnx += s*ccx[0]; tny += s*ccy[0]; tnz += s*ccz[0];
        s = phi[1]*(a0.y + u*b0.y); tnx += s*ccx[1]; tny += s*ccy[1]; tnz += s*ccz[1];
        s = phi[2]*(a0.z + u*b0.z); tnx += s*ccx[2]; tny += s*ccy[2]; tnz += s*ccz[2];
        s = phi[3]*(a0.w + u*b0.w); tnx += s*ccx[3]; tny += s*ccy[3]; tnz += s*ccz[3];
        s = phi[4]*(a1.x + u*b1.x); tnx += s*ccx[4]; tny += s*ccy[4]; tnz += s*ccz[4];
        s = phi[5]*(a1.y + u*b1.y); tnx += s*ccx[5]; tny += s*ccy[5]; tnz += s*ccz[5];
        s = phi[6]*(a1.z + u*b1.z); tnx += s*ccx[6]; tny += s*ccy[6]; tnz += s*ccz[6];
        s = phi[7]*(a1.w + u*b1.w); tnx += s*ccx[7]; tny += s*ccy[7]; tnz += s*ccz[7];
        float qx = ry*tnz - rz*tny;
        float qy = rz*tnx - rx*tnz;
        float qz = rx*tny - ry*tnx;
        e_acc += sx*qx + sy*qy + sz*qz;
    }

    #pragma unroll
    for (int o = 16; o > 0; o >>= 1) e_acc += __shfl_xor_sync(0xffffffffu, e_acc, o);
    if (lane == 0) out[atom] = e_acc;
}

extern "C" void kernel_launch(void* const* d_in, const int* in_sizes, int n_in,
                              void* d_out, int out_size) {
    const float* pos     = (const float*)d_in[0];
    const int*   species = (const int*)  d_in[1];
    const float* mag     = (const float*)d_in[2];
    const int*   eidx    = (const int*)  d_in[3];
    const float* shifts  = (const float*)d_in[4];
    const float* rbc     = (const float*)d_in[5];
    const float* emb     = (const float*)d_in[6];
    const float* sshift  = (const float*)d_in[7];
    const float* sscale  = (const float*)d_in[8];
    const float* mshift  = (const float*)d_in[9];
    const float* mscale  = (const float*)d_in[10];
    const float* aes     = (const float*)d_in[11];
    const float* ws      = (const float*)d_in[12];
    const float* bs      = (const float*)d_in[13];
    const float* wm      = (const float*)d_in[14];
    const float* bm      = (const float*)d_in[15];

    int N = in_sizes[0] / 3;
    int E = in_sizes[3] / 2;

    prep_kernel<<<(N + 255) / 256, 256>>>(pos, species, mag, emb, sshift, sscale,
                                          mshift, mscale, aes, ws, bs, wm, bm, N);

    int smembytes = SM_FLOATS * (int)sizeof(float);
    cudaFuncSetAttribute((const void*)magpot_kernel,
                         cudaFuncAttributeMaxDynamicSharedMemorySize, smembytes);
    // second row of edge_index = j indices
    magpot_kernel<<<(N + 3) / 4, 128, smembytes>>>((const float*)(eidx + E), shifts, rbc,
                                                   (float*)d_out, N);
}

// round 5
// speedup vs baseline: 1.5696x; 1.0815x over previous
#include <cuda_runtime.h>

#define RCUT 5.0f
#define MAXN 65536

// ---- device-global precomputed state (written by prep kernel each launch) ----
__device__ float4 g_pack[2*MAXN];   // per atom: [pos.xyz, species_bits],[mdir.xyz, u]
__device__ float  g_wse[80];        // struct weights / scale
__device__ float  g_wme[256];       // mag weights / scale
__device__ float4 g_fold[16];       // 8 families x 2 float4 (per-edge linear fold weights)
__device__ float4 g_wdA[16];        // dmi weights
__device__ float4 g_wdB[16];        // dmi-mix weights
__device__ float  g_espec[3];
__device__ float  g_c0;
__device__ int    g_tup[36];

__global__ void prep_kernel(const float* __restrict__ pos, const int* __restrict__ species,
                            const float* __restrict__ mag,
                            const float* __restrict__ emb,
                            const float* __restrict__ sshift, const float* __restrict__ sscale,
                            const float* __restrict__ mshift, const float* __restrict__ mscale,
                            const float* __restrict__ aes,
                            const float* __restrict__ ws, const float* __restrict__ bs,
                            const float* __restrict__ wm, const float* __restrict__ bm,
                            int N) {
    int idx = blockIdx.x * 256 + threadIdx.x;
    if (idx < N) {
        float px = pos[idx*3+0], py = pos[idx*3+1], pz = pos[idx*3+2];
        float mx = mag[idx*3+0], my = mag[idx*3+1], mz = mag[idx*3+2];
        float u = mx*mx + my*my + mz*mz;
        float im = (u >= 1e-16f) ? rsqrtf(u) : 0.0f;
        g_pack[2*idx]   = make_float4(px, py, pz, __int_as_float(species[idx]));
        g_pack[2*idx+1] = make_float4(mx*im, my*im, mz*im, u);
    }
    if (blockIdx.x == 0) {
        int t = threadIdx.x;
        for (int d = t; d < 80;  d += 256) g_wse[d] = ws[16 + d] / sscale[d];
        for (int d = t; d < 251; d += 256) g_wme[d] = wm[16 + d] / mscale[d];
        if (t < 64) {
            ((float*)g_wdA)[t] = wm[16 + 83  + t] / mscale[83  + t];
            ((float*)g_wdB)[t] = wm[16 + 163 + t] / mscale[163 + t];
        }
        if (t < 64) {
            // fold families: 0:struct-radial 1:iso 2:sia 3:nbr_amp 4:nbr_ex 5:iso-mix 6:sia-mix 7:nbr_ex-mix
            const int foff[8] = {0, 3, 11, 227, 235, 147, 155, 243};
            int fam = t >> 3, k = t & 7;
            float v;
            if (fam == 0) v = ws[16 + k] / sscale[k];
            else          v = wm[16 + foff[fam] + k] / mscale[foff[fam] + k];
            ((float*)g_fold)[t] = v;
        }
        if (t < 3) {
            float s = aes[t];
            #pragma unroll
            for (int k = 0; k < 16; k++) s += emb[t*16 + k] * (ws[k] + wm[k]);
            g_espec[t] = s;
        }
        if (t < 36) {
            int p = t, a = 0;
            while (p >= 8 - a) { p -= 8 - a; a++; }
            g_tup[t] = (a << 3) | (a + p);
        }
        if (t < 32) {
            float c = 0.0f;
            for (int d = t; d < 80;  d += 32) c += sshift[d] * ws[16 + d] / sscale[d];
            for (int d = t; d < 251; d += 32) c += mshift[d] * wm[16 + d] / mscale[d];
            #pragma unroll
            for (int o = 16; o > 0; o >>= 1) c += __shfl_xor_sync(0xffffffffu, c, o);
            if (t == 0) g_c0 = bs[0] + bm[0] - c;
        }
    }
}

// smem: [0,612) coeffs (9 pairs * 17 float4 rows, padded) ; then per-warp 1312 floats
#define OFF_CO   612
#define WARP_SM  1312
#define SM_FLOATS (OFF_CO + 4 * WARP_SM)

__global__ __launch_bounds__(128, 7)
void magpot_kernel(const float* __restrict__ eidx_j, const float* __restrict__ shifts,
                   const float* __restrict__ rbc,
                   float* __restrict__ out, int N) {
    extern __shared__ float smw[];
    int lane = threadIdx.x & 31, warp = threadIdx.x >> 5;

    // stage coeffs into smem with 17-float4 row stride (bank-skewed per pair)
    {
        const float4* rbc4 = (const float4*)rbc;
        float4* c4s = (float4*)smw;
        for (int t = threadIdx.x; t < 144; t += 128) {
            int pr = t >> 4, q = t & 15;
            c4s[pr*17 + q] = rbc4[pr*16 + q];
        }
    }
    __syncthreads();

    int atom = blockIdx.x * 4 + warp;
    if (atom >= N) return;

    float* buf = smw + OFF_CO + warp * WARP_SM;
    float* S   = buf + 1152;

    // ---------------- edge phase: lane = edge ----------------
    int e = atom * 32 + lane;
    int j = ((const int*)eidx_j)[e];

    float4 ak0 = __ldg(&g_pack[2*atom]);
    float4 ak1 = __ldg(&g_pack[2*atom+1]);
    float4 pk0 = __ldg(&g_pack[2*j]);
    float4 pk1 = __ldg(&g_pack[2*j+1]);

    float rx = pk0.x - ak0.x + shifts[e*3+0];
    float ry = pk0.y - ak0.y + shifts[e*3+1];
    float rz = pk0.z - ak0.z + shifts[e*3+2];
    float d2 = rx*rx + ry*ry + rz*rz;
    float invd = (d2 >= 1e-16f) ? rsqrtf(d2) : 0.0f;
    float dist = d2 * invd;

    float fc = (dist < RCUT) ? (0.5f*__cosf(0.6283185307f*dist) + 0.5f) : 0.0f;
    float xc = 0.08f*d2 - 1.0f;
    float f[8];
    {
        float t0 = 1.0f, t1 = xc;
        f[0] = fc;
        f[1] = 0.5f*(t1 + 1.0f)*fc;
        #pragma unroll
        for (int n = 2; n < 8; n++) { float t2 = 2.0f*xc*t1 - t0; f[n] = 0.5f*(t2 + 1.0f)*fc; t0 = t1; t1 = t2; }
    }
    int spi  = __float_as_int(ak0.w);
    int pair = spi*3 + __float_as_int(pk0.w);
    const float4* c4 = (const float4*)smw;
    float phi[8];
    #pragma unroll
    for (int n = 0; n < 8; n++) {
        float4 a = c4[pair*17 + n*2], b = c4[pair*17 + n*2 + 1];
        phi[n] = a.x*f[0] + a.y*f[1] + a.z*f[2] + a.w*f[3]
               + b.x*f[4] + b.y*f[5] + b.z*f[6] + b.w*f[7];
    }
    float hx = rx*invd, hy = ry*invd, hz = rz*invd;
    float mdjx = pk1.x, mdjy = pk1.y, mdjz = pk1.z, uj = pk1.w;
    float mdx = ak1.x, mdy = ak1.y, mdz = ak1.z, u = ak1.w;
    const float THIRD = 1.0f/3.0f;

    // per-edge fold of descriptors linear in segment sums
    float dotmm = mdx*mdjx + mdy*mdjy + mdz*mdjz;
    float dmh   = mdx*hx + mdy*hy + mdz*hz;
    float mm2   = mdx*mdx + mdy*mdy + mdz*mdz;
    float tq    = dmh*dmh - THIRD*mm2;
    float e_acc = 0.0f;
    #pragma unroll
    for (int h = 0; h < 2; h++) {
        float4 A  = __ldg(&g_fold[0  + h]);
        float4 B0 = __ldg(&g_fold[2  + h]);
        float4 C0 = __ldg(&g_fold[4  + h]);
        float4 D  = __ldg(&g_fold[6  + h]);
        float4 E0 = __ldg(&g_fold[8  + h]);
        float4 Bu = __ldg(&g_fold[10 + h]);
        float4 Cu = __ldg(&g_fold[12 + h]);
        float4 Eu = __ldg(&g_fold[14 + h]);
        e_acc += phi[4*h+0]*(A.x + (B0.x+u*Bu.x)*dotmm + (C0.x+u*Cu.x)*tq + uj*(D.x + (E0.x+u*Eu.x)*dotmm));
        e_acc += phi[4*h+1]*(A.y + (B0.y+u*Bu.y)*dotmm + (C0.y+u*Cu.y)*tq + uj*(D.y + (E0.y+u*Eu.y)*dotmm));
        e_acc += phi[4*h+2]*(A.z + (B0.z+u*Bu.z)*dotmm + (C0.z+u*Cu.z)*tq + uj*(D.z + (E0.z+u*Eu.z)*dotmm));
        e_acc += phi[4*h+3]*(A.w + (B0.w+u*Bu.w)*dotmm + (C0.w+u*Cu.w)*tq + uj*(D.w + (E0.w+u*Eu.w)*dotmm));
    }

    float gv[12];
    gv[0] = hx;          gv[1]  = hy;          gv[2]  = hz;
    gv[3] = hx*hx-THIRD; gv[4]  = hy*hy-THIRD; gv[5]  = hz*hz-THIRD;
    gv[6] = hx*hy;       gv[7]  = hx*hz;       gv[8]  = hy*hz;
    gv[9] = mdjx;        gv[10] = mdjy;        gv[11] = mdjz;

    // ---------------- quarter-split outer-product reduction ----------------
    // S[8k+n] = sum_e phi_n * gv_k : P@0, Q6@24, M@72
    float4* myrow = (float4*)(buf + lane * 36);
    float4* S4 = (float4*)S;
    int col = lane & 7, rg = lane >> 3;
    const float* rbase = buf + (rg * 8) * 36 + col * 4;

    #pragma unroll
    for (int r = 0; r < 3; r++) {
        #pragma unroll
        for (int c = 0; c < 8; c++) {
            int G = r*8 + c, k = G >> 1, h2 = (G & 1) * 4;
            float g = gv[k];
            myrow[c] = make_float4(phi[h2]*g, phi[h2+1]*g, phi[h2+2]*g, phi[h2+3]*g);
        }
        __syncwarp();
        float ax = 0.f, ay = 0.f, az = 0.f, aw = 0.f;
        #pragma unroll
        for (int i = 0; i < 8; i++) {
            const float4 v = *(const float4*)(rbase + i * 36);
            ax += v.x; ay += v.y; az += v.z; aw += v.w;
        }
        ax += __shfl_xor_sync(0xffffffffu, ax, 8);
        ay += __shfl_xor_sync(0xffffffffu, ay, 8);
        az += __shfl_xor_sync(0xffffffffu, az, 8);
        aw += __shfl_xor_sync(0xffffffffu, aw, 8);
        ax += __shfl_xor_sync(0xffffffffu, ax, 16);
        ay += __shfl_xor_sync(0xffffffffu, ay, 16);
        az += __shfl_xor_sync(0xffffffffu, az, 16);
        aw += __shfl_xor_sync(0xffffffffu, aw, 16);
        if (lane < 8) S4[r*8 + lane] = make_float4(ax, ay, az, aw);
        __syncwarp();
    }

    // ---------------- atom phase ----------------
    // mQ[n][c] -> S[96+n*3+c], cc[n][c] -> S[120+n*3+c]
    if (lane < 24) {
        int n = lane / 3, c = lane - n*3;
        int i0 = (c==0) ? 0 : (c+2);
        int i1 = (c==1) ? 1 : (c+3);
        int i2 = (c==2) ? 2 : (c+4);
        S[96 + lane] = S[24+8*i0+n]*mdx + S[24+8*i1+n]*mdy + S[24+8*i2+n]*mdz;
        int c1 = (c==2) ? 0 : c+1;
        int c2 = (c==0) ? 2 : c-1;
        float md1 = (c1==0) ? mdx : ((c1==1) ? mdy : mdz);
        float md2 = (c2==0) ? mdx : ((c2==1) ? mdy : mdz);
        S[120 + lane] = md1*S[72+8*c2+n] - md2*S[72+8*c1+n];
    }
    __syncwarp();

    if (lane == 0) {
        e_acc += __ldg(&g_c0) + __ldg(&g_espec[spi])
               + u*(__ldg(&g_wme[0]) + u*(__ldg(&g_wme[1]) + u*__ldg(&g_wme[2])));
    }

    // struct bilinear: PP triu(36) + QQ triu(36)
    for (int d = lane; d < 72; d += 32) {
        float val;
        if (d < 36) {
            int ab = __ldg(&g_tup[d]); int a = ab >> 3, b = ab & 7;
            val = S[a]*S[b] + S[8+a]*S[8+b] + S[16+a]*S[16+b];
        } else {
            int ab = __ldg(&g_tup[d-36]); int a = ab >> 3, b = ab & 7;
            val = S[24+a]*S[24+b] + S[32+a]*S[32+b] + S[40+a]*S[40+b]
                + 2.0f*(S[48+a]*S[48+b] + S[56+a]*S[56+b] + S[64+a]*S[64+b]);
        }
        e_acc += val * __ldg(&g_wse[8 + d]);
    }

    // sae(64): exactly 2 iterations
    for (int t = lane; t < 64; t += 32) {
        int m = t >> 3, n2 = t & 7;
        float val = S[96+m*3]*S[72+n2] + S[96+m*3+1]*S[80+n2] + S[96+m*3+2]*S[88+n2];
        e_acc += val * __ldg(&g_wme[19 + t]);
    }

    // ---------------- DMI: exclusive-prefix-scan + contraction ----------------
    float ccx[8], ccy[8], ccz[8];
    #pragma unroll
    for (int m = 0; m < 8; m++) {
        ccx[m] = S[120+m*3]; ccy[m] = S[120+m*3+1]; ccz[m] = S[120+m*3+2];
    }
    #pragma unroll
    for (int n = 0; n < 8; n++) {
        float vx = phi[n]*rx, vy = phi[n]*ry, vz = phi[n]*rz;
        float sx = vx, sy = vy, sz = vz;
        #pragma unroll
        for (int o = 1; o < 32; o <<= 1) {
            float tx = __shfl_up_sync(0xffffffffu, sx, o);
            float ty = __shfl_up_sync(0xffffffffu, sy, o);
            float tz = __shfl_up_sync(0xffffffffu, sz, o);
            if (lane >= o) { sx += tx; sy += ty; sz += tz; }
        }
        sx -= vx; sy -= vy; sz -= vz;
        float4 a0 = __ldg(&g_wdA[2*n]), a1 = __ldg(&g_wdA[2*n+1]);
        float4 b0 = __ldg(&g_wdB[2*n]), b1 = __ldg(&g_wdB[2*n+1]);
        float tnx = 0.f, tny = 0.f, tnz = 0.f, s;
        s = phi[0]*(a0.x + u*b0.x); tnx += s*ccx[0]; tny += s*ccy[0]; tnz += s*ccz[0];
        s = phi[1]*(a0.y + u*b0.y); tnx += s*ccx[1]; tny += s*ccy[1]; tnz += s*ccz[1];
        s = phi[2]*(a0.z + u*b0.z); tnx += s*ccx[2]; tny += s*ccy[2]; tnz += s*ccz[2];
        s = phi[3]*(a0.w + u*b0.w); tnx += s*ccx[3]; tny += s*ccy[3]; tnz += s*ccz[3];
        s = phi[4]*(a1.x + u*b1.x); tnx += s*ccx[4]; tny += s*ccy[4]; tnz += s*ccz[4];
        s = phi[5]*(a1.y + u*b1.y); tnx += s*ccx[5]; tny += s*ccy[5]; tnz += s*ccz[5];
        s = phi[6]*(a1.z + u*b1.z); tnx += s*ccx[6]; tny += s*ccy[6]; tnz += s*ccz[6];
        s = phi[7]*(a1.w + u*b1.w); tnx += s*ccx[7]; tny += s*ccy[7]; tnz += s*ccz[7];
        float qx = ry*tnz - rz*tny;
        float qy = rz*tnx - rx*tnz;
        float qz = rx*tny - ry*tnx;
        e_acc += sx*qx + sy*qy + sz*qz;
    }

    #pragma unroll
    for (int o = 16; o > 0; o >>= 1) e_acc += __shfl_xor_sync(0xffffffffu, e_acc, o);
    if (lane == 0) out[atom] = e_acc;
}

extern "C" void kernel_launch(void* const* d_in, const int* in_sizes, int n_in,
                              void* d_out, int out_size) {
    const float* pos     = (const float*)d_in[0];
    const int*   species = (const int*)  d_in[1];
    const float* mag     = (const float*)d_in[2];
    const int*   eidx    = (const int*)  d_in[3];
    const float* shifts  = (const float*)d_in[4];
    const float* rbc     = (const float*)d_in[5];
    const float* emb     = (const float*)d_in[6];
    const float* sshift  = (const float*)d_in[7];
    const float* sscale  = (const float*)d_in[8];
    const float* mshift  = (const float*)d_in[9];
    const float* mscale  = (const float*)d_in[10];
    const float* aes     = (const float*)d_in[11];
    const float* ws      = (const float*)d_in[12];
    const float* bs      = (const float*)d_in[13];
    const float* wm      = (const float*)d_in[14];
    const float* bm      = (const float*)d_in[15];

    int N = in_sizes[0] / 3;
    int E = in_sizes[3] / 2;

    prep_kernel<<<(N + 255) / 256, 256>>>(pos, species, mag, emb, sshift, sscale,
                                          mshift, mscale, aes, ws, bs, wm, bm, N);

    int smembytes = SM_FLOATS * (int)sizeof(float);
    cudaFuncSetAttribute((const void*)magpot_kernel,
                         cudaFuncAttributeMaxDynamicSharedMemorySize, smembytes);
    magpot_kernel<<<(N + 3) / 4, 128, smembytes>>>((const float*)(eidx + E), shifts, rbc,
                                                   (float*)d_out, N);
}

// round 6
// speedup vs baseline: 2.0102x; 1.2807x over previous
#include <cuda_runtime.h>

#define RCUT 5.0f
#define MAXN 65536

// ---- device-global precomputed state (written by prep kernel each launch) ----
__device__ float4 g_pack[2*MAXN];   // per atom: [pos.xyz, species_bits],[mdir.xyz, u]
__device__ float  g_wse[80];
__device__ float  g_wme[256];
__device__ float4 g_fold[16];       // 8 families x 2 float4
__device__ float4 g_wdA[16];
__device__ float4 g_wdB[16];
__device__ float  g_espec[3];
__device__ float  g_c0;
__device__ int    g_tup[36];

__global__ void prep_kernel(const float* __restrict__ pos, const int* __restrict__ species,
                            const float* __restrict__ mag,
                            const float* __restrict__ emb,
                            const float* __restrict__ sshift, const float* __restrict__ sscale,
                            const float* __restrict__ mshift, const float* __restrict__ mscale,
                            const float* __restrict__ aes,
                            const float* __restrict__ ws, const float* __restrict__ bs,
                            const float* __restrict__ wm, const float* __restrict__ bm,
                            int N) {
    int idx = blockIdx.x * 256 + threadIdx.x;
    if (idx < N) {
        float px = pos[idx*3+0], py = pos[idx*3+1], pz = pos[idx*3+2];
        float mx = mag[idx*3+0], my = mag[idx*3+1], mz = mag[idx*3+2];
        float u = mx*mx + my*my + mz*mz;
        float im = (u >= 1e-16f) ? rsqrtf(u) : 0.0f;
        g_pack[2*idx]   = make_float4(px, py, pz, __int_as_float(species[idx]));
        g_pack[2*idx+1] = make_float4(mx*im, my*im, mz*im, u);
    }
    if (blockIdx.x == 0) {
        int t = threadIdx.x;
        for (int d = t; d < 80;  d += 256) g_wse[d] = ws[16 + d] / sscale[d];
        for (int d = t; d < 251; d += 256) g_wme[d] = wm[16 + d] / mscale[d];
        if (t < 64) {
            ((float*)g_wdA)[t] = wm[16 + 83  + t] / mscale[83  + t];
            ((float*)g_wdB)[t] = wm[16 + 163 + t] / mscale[163 + t];
        }
        if (t < 64) {
            const int foff[8] = {0, 3, 11, 227, 235, 147, 155, 243};
            int fam = t >> 3, k = t & 7;
            float v;
            if (fam == 0) v = ws[16 + k] / sscale[k];
            else          v = wm[16 + foff[fam] + k] / mscale[foff[fam] + k];
            ((float*)g_fold)[t] = v;
        }
        if (t < 3) {
            float s = aes[t];
            #pragma unroll
            for (int k = 0; k < 16; k++) s += emb[t*16 + k] * (ws[k] + wm[k]);
            g_espec[t] = s;
        }
        if (t < 36) {
            int p = t, a = 0;
            while (p >= 8 - a) { p -= 8 - a; a++; }
            g_tup[t] = (a << 3) | (a + p);
        }
        if (t < 32) {
            float c = 0.0f;
            for (int d = t; d < 80;  d += 32) c += sshift[d] * ws[16 + d] / sscale[d];
            for (int d = t; d < 251; d += 32) c += mshift[d] * wm[16 + d] / mscale[d];
            #pragma unroll
            for (int o = 16; o > 0; o >>= 1) c += __shfl_xor_sync(0xffffffffu, c, o);
            if (t == 0) g_c0 = bs[0] + bm[0] - c;
        }
    }
}

// smem: [0,612) coeffs (9 pairs * 17 float4, padded); per warp: buf 1152 + 2 atoms * 144
#define OFF_CO   612
#define WARP_SM  1440
#define SM_FLOATS (OFF_CO + 4 * WARP_SM)

// Per-atom S layout (144 floats): S[8k+n], k: 0..2 P(xyz), 3..8 Q(xx,yy,zz,xy,xz,yz),
// 9..11 M(xyz); mQ[n*3+c]@96; cc[n*3+c]@120.

__global__ __launch_bounds__(128, 5)
void magpot_kernel(const int* __restrict__ eidx_j, const float* __restrict__ shifts,
                   const float* __restrict__ rbc,
                   float* __restrict__ out, int N) {
    extern __shared__ float smw[];
    int lane = threadIdx.x & 31, warp = threadIdx.x >> 5;

    {   // stage coeffs (17-float4 row stride)
        const float4* rbc4 = (const float4*)rbc;
        float4* c4s = (float4*)smw;
        for (int t = threadIdx.x; t < 144; t += 128)
            c4s[(t >> 4)*17 + (t & 15)] = rbc4[t];
    }
    __syncthreads();

    int h = lane >> 4, l15 = lane & 15;
    int atom = blockIdx.x * 8 + warp * 2 + h;
    bool valid = (atom < N);
    if (!valid) atom = N - 1;

    float* buf = smw + OFF_CO + warp * WARP_SM;
    float* Sat = buf + 1152 + h * 144;

    float4 ak0 = __ldg(&g_pack[2*atom]);
    float4 ak1 = __ldg(&g_pack[2*atom+1]);
    int spi = __float_as_int(ak0.w);
    float mdx = ak1.x, mdy = ak1.y, mdz = ak1.z, u = ak1.w;
    float mm2 = mdx*mdx + mdy*mdy + mdz*mdz;
    const float THIRD = 1.0f/3.0f;

    int2 j01 = ((const int2*)eidx_j)[atom*16 + l15];
    const float2* sh2 = (const float2*)shifts;
    int sbase = atom*48 + l15*3;
    float2 sh0 = sh2[sbase], sh1 = sh2[sbase+1], sh2v = sh2[sbase+2];

    // ---------------- edge phase: 2 edges per lane ----------------
    float phi[2][8], rr[2][3], gv[2][12];
    float dmv[2], tqv[2], ujv[2];
    const float4* c4 = (const float4*)smw;
    #pragma unroll
    for (int ee = 0; ee < 2; ee++) {
        int j = ee ? j01.y : j01.x;
        float sx = ee ? sh1.y : sh0.x;
        float sy = ee ? sh2v.x : sh0.y;
        float sz = ee ? sh2v.y : sh1.x;
        float4 pk0 = __ldg(&g_pack[2*j]);
        float4 pk1 = __ldg(&g_pack[2*j+1]);
        float rx = pk0.x - ak0.x + sx;
        float ry = pk0.y - ak0.y + sy;
        float rz = pk0.z - ak0.z + sz;
        float d2 = rx*rx + ry*ry + rz*rz;
        float invd = (d2 >= 1e-16f) ? rsqrtf(d2) : 0.0f;
        float dist = d2 * invd;
        float fc = (dist < RCUT) ? (0.5f*__cosf(0.6283185307f*dist) + 0.5f) : 0.0f;
        float xc = 0.08f*d2 - 1.0f;
        float f[8];
        {
            float t0 = 1.0f, t1 = xc;
            f[0] = fc;
            f[1] = 0.5f*(t1 + 1.0f)*fc;
            #pragma unroll
            for (int n = 2; n < 8; n++) { float t2 = 2.0f*xc*t1 - t0; f[n] = 0.5f*(t2+1.0f)*fc; t0 = t1; t1 = t2; }
        }
        int pair = spi*3 + __float_as_int(pk0.w);
        #pragma unroll
        for (int n = 0; n < 8; n++) {
            float4 a = c4[pair*17 + n*2], b = c4[pair*17 + n*2 + 1];
            phi[ee][n] = a.x*f[0] + a.y*f[1] + a.z*f[2] + a.w*f[3]
                       + b.x*f[4] + b.y*f[5] + b.z*f[6] + b.w*f[7];
        }
        float hx = rx*invd, hy = ry*invd, hz = rz*invd;
        gv[ee][0] = hx;           gv[ee][1]  = hy;          gv[ee][2]  = hz;
        gv[ee][3] = hx*hx-THIRD;  gv[ee][4]  = hy*hy-THIRD; gv[ee][5]  = hz*hz-THIRD;
        gv[ee][6] = hx*hy;        gv[ee][7]  = hx*hz;       gv[ee][8]  = hy*hz;
        gv[ee][9] = pk1.x;        gv[ee][10] = pk1.y;       gv[ee][11] = pk1.z;
        rr[ee][0] = rx; rr[ee][1] = ry; rr[ee][2] = rz;
        dmv[ee] = mdx*pk1.x + mdy*pk1.y + mdz*pk1.z;
        float dmh = mdx*hx + mdy*hy + mdz*hz;
        tqv[ee] = dmh*dmh - THIRD*mm2;
        ujv[ee] = pk1.w;
    }

    // linear-descriptor fold (weights loaded once, serving both edges)
    float e_acc = 0.0f;
    #pragma unroll
    for (int g = 0; g < 2; g++) {
        float4 A  = __ldg(&g_fold[0  + g]);
        float4 B0 = __ldg(&g_fold[2  + g]);
        float4 C0 = __ldg(&g_fold[4  + g]);
        float4 D  = __ldg(&g_fold[6  + g]);
        float4 E0 = __ldg(&g_fold[8  + g]);
        float4 Bu = __ldg(&g_fold[10 + g]);
        float4 Cu = __ldg(&g_fold[12 + g]);
        float4 Eu = __ldg(&g_fold[14 + g]);
        #pragma unroll
        for (int c = 0; c < 4; c++) {
            int n = 4*g + c;
            float p0 = phi[0][n], p1 = phi[1][n];
            float pa = p0 + p1;
            float pb = p0*dmv[0] + p1*dmv[1];
            float pc = p0*tqv[0] + p1*tqv[1];
            float pd = p0*ujv[0] + p1*ujv[1];
            float pe = p0*ujv[0]*dmv[0] + p1*ujv[1]*dmv[1];
            float Ac  = (c==0)?A.x :(c==1)?A.y :(c==2)?A.z :A.w;
            float B0c = (c==0)?B0.x:(c==1)?B0.y:(c==2)?B0.z:B0.w;
            float C0c = (c==0)?C0.x:(c==1)?C0.y:(c==2)?C0.z:C0.w;
            float Dc  = (c==0)?D.x :(c==1)?D.y :(c==2)?D.z :D.w;
            float E0c = (c==0)?E0.x:(c==1)?E0.y:(c==2)?E0.z:E0.w;
            float Buc = (c==0)?Bu.x:(c==1)?Bu.y:(c==2)?Bu.z:Bu.w;
            float Cuc = (c==0)?Cu.x:(c==1)?Cu.y:(c==2)?Cu.z:Cu.w;
            float Euc = (c==0)?Eu.x:(c==1)?Eu.y:(c==2)?Eu.z:Eu.w;
            e_acc += pa*Ac + pb*(B0c + u*Buc) + pc*(C0c + u*Cuc)
                   + pd*Dc + pe*(E0c + u*Euc);
        }
    }

    // ---------------- segmented quarter-split reduction (2 atoms/warp) ----------------
    float4* myrow = (float4*)(buf + lane * 36);
    float4* S4at = (float4*)Sat;
    int col = lane & 7, rg = lane >> 3;
    const float* rbase = buf + (rg * 8) * 36 + col * 4;

    #pragma unroll
    for (int r = 0; r < 3; r++) {
        #pragma unroll
        for (int c = 0; c < 8; c++) {
            int G = r*8 + c, k = G >> 1, h2 = (G & 1) * 4;
            float g0 = gv[0][k], g1 = gv[1][k];
            myrow[c] = make_float4(phi[0][h2+0]*g0 + phi[1][h2+0]*g1,
                                   phi[0][h2+1]*g0 + phi[1][h2+1]*g1,
                                   phi[0][h2+2]*g0 + phi[1][h2+2]*g1,
                                   phi[0][h2+3]*g0 + phi[1][h2+3]*g1);
        }
        __syncwarp();
        float ax = 0.f, ay = 0.f, az = 0.f, aw = 0.f;
        #pragma unroll
        for (int i = 0; i < 8; i++) {
            const float4 v = *(const float4*)(rbase + i * 36);
            ax += v.x; ay += v.y; az += v.z; aw += v.w;
        }
        ax += __shfl_xor_sync(0xffffffffu, ax, 8);
        ay += __shfl_xor_sync(0xffffffffu, ay, 8);
        az += __shfl_xor_sync(0xffffffffu, az, 8);
        aw += __shfl_xor_sync(0xffffffffu, aw, 8);
        if ((lane & 8) == 0) S4at[r*8 + col] = make_float4(ax, ay, az, aw);
        __syncwarp();
    }

    // ---------------- atom phase (16 lanes per atom) ----------------
    // mQ[n][c] -> Sat[96+n*3+c], cc[n][c] -> Sat[120+n*3+c]
    for (int t = l15; t < 24; t += 16) {
        int n = t / 3, c = t - n*3;
        int i0 = (c==0) ? 24 : ((c==1) ? 48 : 56);
        int i1 = (c==0) ? 48 : ((c==1) ? 32 : 64);
        int i2 = (c==0) ? 56 : ((c==1) ? 64 : 40);
        Sat[96 + t] = Sat[i0+n]*mdx + Sat[i1+n]*mdy + Sat[i2+n]*mdz;
        int c1 = (c==2) ? 0 : c+1;
        int c2 = (c==0) ? 2 : c-1;
        float md1 = (c1==0) ? mdx : ((c1==1) ? mdy : mdz);
        float md2 = (c2==0) ? mdx : ((c2==1) ? mdy : mdz);
        Sat[120 + t] = md1*Sat[72+8*c2+n] - md2*Sat[72+8*c1+n];
    }
    __syncwarp();

    if (l15 == 0) {
        e_acc += __ldg(&g_c0) + __ldg(&g_espec[spi])
               + u*(__ldg(&g_wme[0]) + u*(__ldg(&g_wme[1]) + u*__ldg(&g_wme[2])));
    }

    // struct bilinear: PP triu(36) + QQ triu(36)
    for (int d = l15; d < 72; d += 16) {
        float val;
        if (d < 36) {
            int ab = __ldg(&g_tup[d]); int a = ab >> 3, b = ab & 7;
            val = Sat[a]*Sat[b] + Sat[8+a]*Sat[8+b] + Sat[16+a]*Sat[16+b];
        } else {
            int ab = __ldg(&g_tup[d-36]); int a = ab >> 3, b = ab & 7;
            val = Sat[24+a]*Sat[24+b] + Sat[32+a]*Sat[32+b] + Sat[40+a]*Sat[40+b]
                + 2.0f*(Sat[48+a]*Sat[48+b] + Sat[56+a]*Sat[56+b] + Sat[64+a]*Sat[64+b]);
        }
        e_acc += val * __ldg(&g_wse[8 + d]);
    }

    // sae(64)
    for (int t = l15; t < 64; t += 16) {
        int m = t >> 3, n2 = t & 7;
        float val = Sat[96+m*3]*Sat[72+n2] + Sat[96+m*3+1]*Sat[80+n2] + Sat[96+m*3+2]*Sat[88+n2];
        e_acc += val * __ldg(&g_wme[19 + t]);
    }

    // ---------------- DMI: segmented 4-step scan + local pair ----------------
    float ccx[8], ccy[8], ccz[8];
    #pragma unroll
    for (int m = 0; m < 8; m++) {
        ccx[m] = Sat[120+m*3]; ccy[m] = Sat[120+m*3+1]; ccz[m] = Sat[120+m*3+2];
    }
    float r0x = rr[0][0], r0y = rr[0][1], r0z = rr[0][2];
    float r1x = rr[1][0], r1y = rr[1][1], r1z = rr[1][2];
    #pragma unroll
    for (int n = 0; n < 8; n++) {
        float vx = phi[0][n]*r0x + phi[1][n]*r1x;
        float vy = phi[0][n]*r0y + phi[1][n]*r1y;
        float vz = phi[0][n]*r0z + phi[1][n]*r1z;
        float sx = vx, sy = vy, sz = vz;
        #pragma unroll
        for (int o = 1; o < 16; o <<= 1) {
            float tx = __shfl_up_sync(0xffffffffu, sx, o);
            float ty = __shfl_up_sync(0xffffffffu, sy, o);
            float tz = __shfl_up_sync(0xffffffffu, sz, o);
            if (l15 >= o) { sx += tx; sy += ty; sz += tz; }
        }
        sx -= vx; sy -= vy; sz -= vz;   // exclusive prefix (within atom segment)
        float4 a0 = __ldg(&g_wdA[2*n]), a1 = __ldg(&g_wdA[2*n+1]);
        float4 b0 = __ldg(&g_wdB[2*n]), b1 = __ldg(&g_wdB[2*n+1]);
        float t0x = 0.f, t0y = 0.f, t0z = 0.f;
        float t1x = 0.f, t1y = 0.f, t1z = 0.f;
        #pragma unroll
        for (int m = 0; m < 8; m++) {
            float wm;
            if (m == 0) wm = a0.x + u*b0.x;
            else if (m == 1) wm = a0.y + u*b0.y;
            else if (m == 2) wm = a0.z + u*b0.z;
            else if (m == 3) wm = a0.w + u*b0.w;
            else if (m == 4) wm = a1.x + u*b1.x;
            else if (m == 5) wm = a1.y + u*b1.y;
            else if (m == 6) wm = a1.z + u*b1.z;
            else             wm = a1.w + u*b1.w;
            float s0 = phi[0][m]*wm, s1 = phi[1][m]*wm;
            t0x += s0*ccx[m]; t0y += s0*ccy[m]; t0z += s0*ccz[m];
            t1x += s1*ccx[m]; t1y += s1*ccy[m]; t1z += s1*ccz[m];
        }
        float q0x = r0y*t0z - r0z*t0y;
        float q0y = r0z*t0x - r0x*t0z;
        float q0z = r0x*t0y - r0y*t0x;
        float q1x = r1y*t1z - r1z*t1y;
        float q1y = r1z*t1x - r1x*t1z;
        float q1z = r1x*t1y - r1y*t1x;
        e_acc += sx*(q0x+q1x) + sy*(q0y+q1y) + sz*(q0z+q1z)
               + phi[0][n]*(r0x*q1x + r0y*q1y + r0z*q1z);
    }

    // segmented final reduce (within 16-lane half)
    #pragma unroll
    for (int o = 8; o > 0; o >>= 1) e_acc += __shfl_xor_sync(0xffffffffu, e_acc, o);
    if (l15 == 0 && valid) out[atom] = e_acc;
}

extern "C" void kernel_launch(void* const* d_in, const int* in_sizes, int n_in,
                              void* d_out, int out_size) {
    const float* pos     = (const float*)d_in[0];
    const int*   species = (const int*)  d_in[1];
    const float* mag     = (const float*)d_in[2];
    const int*   eidx    = (const int*)  d_in[3];
    const float* shifts  = (const float*)d_in[4];
    const float* rbc     = (const float*)d_in[5];
    const float* emb     = (const float*)d_in[6];
    const float* sshift  = (const float*)d_in[7];
    const float* sscale  = (const float*)d_in[8];
    const float* mshift  = (const float*)d_in[9];
    const float* mscale  = (const float*)d_in[10];
    const float* aes     = (const float*)d_in[11];
    const float* ws      = (const float*)d_in[12];
    const float* bs      = (const float*)d_in[13];
    const float* wm      = (const float*)d_in[14];
    const float* bm      = (const float*)d_in[15];

    int N = in_sizes[0] / 3;
    int E = in_sizes[3] / 2;

    prep_kernel<<<(N + 255) / 256, 256>>>(pos, species, mag, emb, sshift, sscale,
                                          mshift, mscale, aes, ws, bs, wm, bm, N);

    int smembytes = SM_FLOATS * (int)sizeof(float);
    cudaFuncSetAttribute((const void*)magpot_kernel,
                         cudaFuncAttributeMaxDynamicSharedMemorySize, smembytes);
    magpot_kernel<<<(N + 7) / 8, 128, smembytes>>>(eidx + E, shifts, rbc,
                                                   (float*)d_out, N);
}